// round 2
// baseline (speedup 1.0000x reference)
#include <cuda_runtime.h>
#include <math.h>

// Problem constants
#define BATCH 4096
#define NVAR  16
#define DDIM  256
#define FEAT  (NVAR * DDIM)   // 4096

// -------------------- scratch (device globals; no allocation allowed) ------
__device__ float g_buf0[(size_t)BATCH * FEAT];
__device__ float g_buf1[(size_t)BATCH * FEAT];
__device__ float g_buf2[(size_t)BATCH * FEAT];
__device__ float g_buf3[(size_t)BATCH * FEAT];

// -------------------- generic tiled FP32 GEMM ------------------------------
// C[m, c] = act( sum_k A[m,k] * W[k,c] + bias[c] )
// blockIdx.z = batch index (per-variable GEMMs); offsets via s*n strides.
// BM=BN=128, BK=16, 256 threads, 8x8 register tile per thread.
// All dims are multiples of the tile sizes -> no guards.
template <int ACT>  // 0 = none(+bias), 1 = ELU(+bias)
__global__ __launch_bounds__(256, 2)
void gemm_k(const float* __restrict__ A, int lda, long sAn,
            const float* __restrict__ W, int ldw, long sWn,
            const float* __restrict__ bias, int sBn,
            float* __restrict__ C, int ldc, long sCn,
            int K)
{
    const int n = blockIdx.z;
    A    += (long)n * sAn;
    W    += (long)n * sWn;
    bias += (long)n * sBn;
    C    += (long)n * sCn;

    const int bm  = blockIdx.y * 128;
    const int bn  = blockIdx.x * 128;
    const int tid = threadIdx.x;
    const int tx  = tid & 15;
    const int ty  = tid >> 4;

    __shared__ float As[16][128];
    __shared__ float Bs[16][128];

    float acc[8][8];
#pragma unroll
    for (int i = 0; i < 8; i++)
#pragma unroll
        for (int j = 0; j < 8; j++) acc[i][j] = 0.f;

    for (int k0 = 0; k0 < K; k0 += 16) {
        // Load A tile 128x16 (512 float4 loads, 2 per thread), store transposed.
#pragma unroll
        for (int t = 0; t < 2; t++) {
            int l   = tid + t * 256;
            int row = l >> 2;
            int kk  = (l & 3) << 2;
            float4 v = *(const float4*)(A + (long)(bm + row) * lda + k0 + kk);
            As[kk + 0][row] = v.x;
            As[kk + 1][row] = v.y;
            As[kk + 2][row] = v.z;
            As[kk + 3][row] = v.w;
        }
        // Load W tile 16x128 directly.
#pragma unroll
        for (int t = 0; t < 2; t++) {
            int l  = tid + t * 256;
            int kr = l >> 5;
            int nc = (l & 31) << 2;
            *(float4*)(&Bs[kr][nc]) =
                *(const float4*)(W + (long)(k0 + kr) * ldw + bn + nc);
        }
        __syncthreads();

#pragma unroll
        for (int k = 0; k < 16; k++) {
            float a[8], b[8];
            *(float4*)(a)     = *(const float4*)(&As[k][ty * 8]);
            *(float4*)(a + 4) = *(const float4*)(&As[k][ty * 8 + 4]);
            *(float4*)(b)     = *(const float4*)(&Bs[k][tx * 8]);
            *(float4*)(b + 4) = *(const float4*)(&Bs[k][tx * 8 + 4]);
#pragma unroll
            for (int i = 0; i < 8; i++)
#pragma unroll
                for (int j = 0; j < 8; j++)
                    acc[i][j] = fmaf(a[i], b[j], acc[i][j]);
        }
        __syncthreads();
    }

    // Epilogue: bias + activation, float4 stores.
    float bcol[8];
#pragma unroll
    for (int j = 0; j < 8; j++) bcol[j] = bias[bn + tx * 8 + j];

#pragma unroll
    for (int i = 0; i < 8; i++) {
        float* Crow = C + (long)(bm + ty * 8 + i) * ldc + bn + tx * 8;
#pragma unroll
        for (int j4 = 0; j4 < 8; j4 += 4) {
            float4 o;
            float v0 = acc[i][j4 + 0] + bcol[j4 + 0];
            float v1 = acc[i][j4 + 1] + bcol[j4 + 1];
            float v2 = acc[i][j4 + 2] + bcol[j4 + 2];
            float v3 = acc[i][j4 + 3] + bcol[j4 + 3];
            if (ACT == 1) {
                v0 = v0 > 0.f ? v0 : expm1f(v0);
                v1 = v1 > 0.f ? v1 : expm1f(v1);
                v2 = v2 > 0.f ? v2 : expm1f(v2);
                v3 = v3 > 0.f ? v3 : expm1f(v3);
            }
            o.x = v0; o.y = v1; o.z = v2; o.w = v3;
            *(float4*)(Crow + j4) = o;
        }
    }
}

// -------------------- GLU elementwise: a = sigmoid(a) * b -------------------
__global__ void glu_k(float* __restrict__ a, const float* __restrict__ b, size_t n)
{
    size_t i = (size_t)blockIdx.x * blockDim.x + threadIdx.x;
    if (i < n) {
        float s = 1.f / (1.f + expf(-a[i]));
        a[i] = s * b[i];
    }
}

// -------------------- LN(4096) + softmax over variable axis ----------------
// One block per batch row. c = LN(x_flat + g); w[b,n,d] = softmax_n c[b,n,d]
__global__ __launch_bounds__(256)
void ln_softmax_k(const float* __restrict__ x, const float* __restrict__ g,
                  const float* __restrict__ gamma, const float* __restrict__ beta,
                  float* __restrict__ w)
{
    __shared__ float s[FEAT];
    __shared__ float red[8];
    const int b = blockIdx.x;
    const int t = threadIdx.x;
    const int lane = t & 31, wid = t >> 5;
    const float* xb = x + (long)b * FEAT;
    const float* gb = g + (long)b * FEAT;

    float lsum = 0.f;
    for (int i = t; i < FEAT; i += 256) {
        float v = xb[i] + gb[i];
        s[i] = v;
        lsum += v;
    }
#pragma unroll
    for (int o = 16; o; o >>= 1) lsum += __shfl_xor_sync(0xffffffff, lsum, o);
    if (lane == 0) red[wid] = lsum;
    __syncthreads();
    float tot = 0.f;
#pragma unroll
    for (int i = 0; i < 8; i++) tot += red[i];
    float mean = tot * (1.f / FEAT);
    __syncthreads();

    float lvar = 0.f;
    for (int i = t; i < FEAT; i += 256) {
        float d = s[i] - mean;
        lvar += d * d;
    }
#pragma unroll
    for (int o = 16; o; o >>= 1) lvar += __shfl_xor_sync(0xffffffff, lvar, o);
    if (lane == 0) red[wid] = lvar;
    __syncthreads();
    float vtot = 0.f;
#pragma unroll
    for (int i = 0; i < 8; i++) vtot += red[i];
    float rstd = rsqrtf(vtot * (1.f / FEAT) + 1e-5f);

    for (int i = t; i < FEAT; i += 256)
        s[i] = (s[i] - mean) * rstd * gamma[i] + beta[i];
    __syncthreads();

    // softmax over n for feature d = t  (stride-256 reads, conflict-free)
    float c[NVAR];
    float m = -1e30f;
#pragma unroll
    for (int n = 0; n < NVAR; n++) {
        c[n] = s[n * DDIM + t];
        m = fmaxf(m, c[n]);
    }
    float sum = 0.f;
#pragma unroll
    for (int n = 0; n < NVAR; n++) {
        c[n] = expf(c[n] - m);
        sum += c[n];
    }
    float inv = 1.f / sum;
    float* wb = w + (long)b * FEAT;
#pragma unroll
    for (int n = 0; n < NVAR; n++) wb[n * DDIM + t] = c[n] * inv;
}

// -------------------- per-(b,n) LN(256) + weighted combine -----------------
// out[b,d] = sum_n w[b,n,d] * LN_256(x[b,n,:] + gv[b,n,:]; vlng[n], vlnb[n])[d]
__global__ __launch_bounds__(256)
void combine_k(const float* __restrict__ x, const float* __restrict__ gv,
               const float* __restrict__ w, const float* __restrict__ vlng,
               const float* __restrict__ vlnb, float* __restrict__ out)
{
    __shared__ float red[8];
    const int b = blockIdx.x;
    const int t = threadIdx.x;
    const int lane = t & 31, wid = t >> 5;

    float acc = 0.f;
    for (int n = 0; n < NVAR; n++) {
        long idx = (long)b * FEAT + n * DDIM + t;
        float v = x[idx] + gv[idx];

        // mean over 256
        float s1 = v;
#pragma unroll
        for (int o = 16; o; o >>= 1) s1 += __shfl_xor_sync(0xffffffff, s1, o);
        __syncthreads();
        if (lane == 0) red[wid] = s1;
        __syncthreads();
        float tot = 0.f;
#pragma unroll
        for (int i = 0; i < 8; i++) tot += red[i];
        float mean = tot * (1.f / DDIM);

        // var over 256 (two-pass)
        float d = v - mean;
        float s2 = d * d;
#pragma unroll
        for (int o = 16; o; o >>= 1) s2 += __shfl_xor_sync(0xffffffff, s2, o);
        __syncthreads();
        if (lane == 0) red[wid] = s2;
        __syncthreads();
        float vtot = 0.f;
#pragma unroll
        for (int i = 0; i < 8; i++) vtot += red[i];
        float rstd = rsqrtf(vtot * (1.f / DDIM) + 1e-5f);

        float yv = d * rstd * vlng[n * DDIM + t] + vlnb[n * DDIM + t];
        acc += w[idx] * yv;
    }
    out[(long)b * DDIM + t] = acc;
}

// -------------------- launch ------------------------------------------------
extern "C" void kernel_launch(void* const* d_in, const int* in_sizes, int n_in,
                              void* d_out, int out_size)
{
    const float* x    = (const float*)d_in[0];
    const float* vW2  = (const float*)d_in[1];
    const float* vb2  = (const float*)d_in[2];
    const float* vW1  = (const float*)d_in[3];
    const float* vb1  = (const float*)d_in[4];
    const float* vW4  = (const float*)d_in[5];
    const float* vb4  = (const float*)d_in[6];
    const float* vW5  = (const float*)d_in[7];
    const float* vb5  = (const float*)d_in[8];
    const float* vlng = (const float*)d_in[9];
    const float* vlnb = (const float*)d_in[10];
    const float* cW2  = (const float*)d_in[11];
    const float* cb2  = (const float*)d_in[12];
    const float* cW1  = (const float*)d_in[13];
    const float* cb1  = (const float*)d_in[14];
    const float* cW4  = (const float*)d_in[15];
    const float* cb4  = (const float*)d_in[16];
    const float* cW5  = (const float*)d_in[17];
    const float* cb5  = (const float*)d_in[18];
    const float* clng = (const float*)d_in[19];
    const float* clnb = (const float*)d_in[20];
    float* out = (float*)d_out;

    float *buf0, *buf1, *buf2, *buf3;
    cudaGetSymbolAddress((void**)&buf0, g_buf0);
    cudaGetSymbolAddress((void**)&buf1, g_buf1);
    cudaGetSymbolAddress((void**)&buf2, g_buf2);
    cudaGetSymbolAddress((void**)&buf3, g_buf3);

    const size_t NE = (size_t)BATCH * FEAT;

    dim3 gridC(FEAT / 128, BATCH / 128, 1);   // concat GEMMs: 32 x 32
    dim3 gridV(DDIM / 128, BATCH / 128, NVAR); // per-var:      2 x 32 x 16
    dim3 blk(256);

    // ---- concat GRN ----
    // h = elu(flat @ cW2 + cb2) -> buf0
    gemm_k<1><<<gridC, blk>>>(x, FEAT, 0, cW2, FEAT, 0, cb2, 0,
                              buf0, FEAT, 0, FEAT);
    // e1 = h @ cW1 + cb1 -> buf1
    gemm_k<0><<<gridC, blk>>>(buf0, FEAT, 0, cW1, FEAT, 0, cb1, 0,
                              buf1, FEAT, 0, FEAT);
    // t4 = e1 @ cW4 + cb4 -> buf2 ; t5 = e1 @ cW5 + cb5 -> buf3
    gemm_k<0><<<gridC, blk>>>(buf1, FEAT, 0, cW4, FEAT, 0, cb4, 0,
                              buf2, FEAT, 0, FEAT);
    gemm_k<0><<<gridC, blk>>>(buf1, FEAT, 0, cW5, FEAT, 0, cb5, 0,
                              buf3, FEAT, 0, FEAT);
    // g = sigmoid(t4)*t5 -> buf2
    glu_k<<<(unsigned)(NE / 256), 256>>>(buf2, buf3, NE);
    // c = LN(flat + g); w = softmax_n(c) -> buf3
    ln_softmax_k<<<BATCH, 256>>>(x, buf2, clng, clnb, buf3);

    // ---- per-variable GRNs (batched over n via blockIdx.z) ----
    // hv = elu(x_n @ vW2_n + vb2_n) -> buf0
    gemm_k<1><<<gridV, blk>>>(x, FEAT, DDIM, vW2, DDIM, (long)DDIM * DDIM,
                              vb2, DDIM, buf0, FEAT, DDIM, DDIM);
    // e1v = hv @ vW1 + vb1 -> buf1
    gemm_k<0><<<gridV, blk>>>(buf0, FEAT, DDIM, vW1, DDIM, (long)DDIM * DDIM,
                              vb1, DDIM, buf1, FEAT, DDIM, DDIM);
    // t4v -> buf2 ; t5v -> buf0
    gemm_k<0><<<gridV, blk>>>(buf1, FEAT, DDIM, vW4, DDIM, (long)DDIM * DDIM,
                              vb4, DDIM, buf2, FEAT, DDIM, DDIM);
    gemm_k<0><<<gridV, blk>>>(buf1, FEAT, DDIM, vW5, DDIM, (long)DDIM * DDIM,
                              vb5, DDIM, buf0, FEAT, DDIM, DDIM);
    // gv = sigmoid(t4v)*t5v -> buf2
    glu_k<<<(unsigned)(NE / 256), 256>>>(buf2, buf0, NE);

    // ---- final combine ----
    combine_k<<<BATCH, 256>>>(x, buf2, buf3, vlng, vlnb, out);
}

// round 4
// speedup vs baseline: 2.2091x; 2.2091x over previous
#include <cuda_runtime.h>
#include <cuda_bf16.h>
#include <math.h>
#include <stdint.h>

#define BATCH 4096
#define NVAR  16
#define DDIM  256
#define FEAT  4096
#define NELEM ((size_t)BATCH * FEAT)     // 16,777,216
#define VWN   ((size_t)NVAR * DDIM * DDIM)

// ---------------- scratch (device globals; allocation forbidden) -----------
__device__ __align__(256) float g_buf0[NELEM];
__device__ __align__(256) float g_buf1[NELEM];
__device__ __align__(256) float g_buf2[NELEM];
__device__ __align__(256) float g_buf3[NELEM];
__device__ __align__(256) __nv_bfloat16 g_xh[NELEM], g_xl[NELEM];
__device__ __align__(256) __nv_bfloat16 g_hh[NELEM], g_hl[NELEM];
__device__ __align__(256) __nv_bfloat16 g_eh[NELEM], g_el[NELEM];
__device__ __align__(256) __nv_bfloat16 g_cW2h[NELEM], g_cW2l[NELEM];
__device__ __align__(256) __nv_bfloat16 g_cW1h[NELEM], g_cW1l[NELEM];
__device__ __align__(256) __nv_bfloat16 g_cW4h[NELEM], g_cW4l[NELEM];
__device__ __align__(256) __nv_bfloat16 g_cW5h[NELEM], g_cW5l[NELEM];
__device__ __align__(256) __nv_bfloat16 g_vW2h[VWN], g_vW2l[VWN];
__device__ __align__(256) __nv_bfloat16 g_vW1h[VWN], g_vW1l[VWN];
__device__ __align__(256) __nv_bfloat16 g_vW4h[VWN], g_vW4l[VWN];
__device__ __align__(256) __nv_bfloat16 g_vW5h[VWN], g_vW5l[VWN];

// ---------------- helpers ---------------------------------------------------
__device__ __forceinline__ uint32_t smem_u32(const void* p) {
    uint32_t a;
    asm("{ .reg .u64 t; cvta.to.shared.u64 t, %1; cvt.u32.u64 %0, t; }"
        : "=r"(a) : "l"(p));
    return a;
}

#define CP_ASYNC16(dst, src) \
    asm volatile("cp.async.cg.shared.global [%0], [%1], 16;" :: "r"(dst), "l"(src))
#define CP_COMMIT() asm volatile("cp.async.commit_group;" ::: "memory")
#define CP_WAIT2()  asm volatile("cp.async.wait_group 2;" ::: "memory")

#define LDSM4(r, a) \
    asm volatile("ldmatrix.sync.aligned.m8n8.x4.shared.b16 {%0,%1,%2,%3}, [%4];" \
                 : "=r"((r)[0]), "=r"((r)[1]), "=r"((r)[2]), "=r"((r)[3]) : "r"(a))

__device__ __forceinline__ void mma16816(float* d, const uint32_t* a,
                                         uint32_t b0, uint32_t b1) {
    asm volatile(
        "mma.sync.aligned.m16n8k16.row.col.f32.bf16.bf16.f32 "
        "{%0,%1,%2,%3}, {%4,%5,%6,%7}, {%8,%9}, {%0,%1,%2,%3};"
        : "+f"(d[0]), "+f"(d[1]), "+f"(d[2]), "+f"(d[3])
        : "r"(a[0]), "r"(a[1]), "r"(a[2]), "r"(a[3]), "r"(b0), "r"(b1));
}

__device__ __forceinline__ uint32_t pack2bf16(float v0, float v1) {
    __nv_bfloat162 t = __floats2bfloat162_rn(v0, v1);
    return *reinterpret_cast<uint32_t*>(&t);
}

// ---------------- GEMM (mma.sync bf16, 3-product split) --------------------
// BM=BN=128, BK=32, 256 threads, 4-stage cp.async pipeline.
#define BM 128
#define BN 128
#define BK 32
#define RS 40                           // smem row stride in bf16 elems (80 B)
#define TILEB (128 * RS * 2)            // 10240 B per (matrix, hi|lo) tile
#define STAGEB (4 * TILEB)              // 40960 B per stage
#define NSTAGE 4
#define GEMM_SMEM (NSTAGE * STAGEB)     // 163840 B

__device__ __forceinline__ void load_chunk(
    uint32_t s0, int tid, int k0,
    const __nv_bfloat16* __restrict__ Ah, const __nv_bfloat16* __restrict__ Al,
    int lda, int bm,
    const __nv_bfloat16* __restrict__ Bh, const __nv_bfloat16* __restrict__ Bl,
    int ldb, int bn)
{
#pragma unroll
    for (int r = 0; r < 2; r++) {
        int e = tid + r * 256;
        int row = e >> 2, seg = e & 3;
        uint32_t off = (uint32_t)row * (RS * 2) + seg * 16;
        size_t ga = (size_t)(bm + row) * lda + k0 + seg * 8;
        size_t gb = (size_t)(bn + row) * ldb + k0 + seg * 8;
        CP_ASYNC16(s0 + off,             Ah + ga);
        CP_ASYNC16(s0 + TILEB + off,     Al + ga);
        CP_ASYNC16(s0 + 2 * TILEB + off, Bh + gb);
        CP_ASYNC16(s0 + 3 * TILEB + off, Bl + gb);
    }
}

// ACT: 0 none, 1 ELU.  SPLIT: 1 -> write bf16 hi/lo, 0 -> write fp32.
template <int ACT, int SPLIT>
__global__ __launch_bounds__(256, 1)
void tgemm_k(const __nv_bfloat16* __restrict__ Ah, const __nv_bfloat16* __restrict__ Al,
             int lda, long sAn,
             const __nv_bfloat16* __restrict__ Bh, const __nv_bfloat16* __restrict__ Bl,
             int ldb, long sBn,
             const float* __restrict__ bias, int sBiasN,
             float* __restrict__ Cf, __nv_bfloat16* __restrict__ Ch,
             __nv_bfloat16* __restrict__ Cl, int ldc, long sCn,
             int K)
{
    extern __shared__ char smem[];
    const uint32_t sbase = smem_u32(smem);
    const int tid = threadIdx.x;
    const int nb = blockIdx.z;
    Ah += (size_t)nb * sAn;  Al += (size_t)nb * sAn;
    Bh += (size_t)nb * sBn;  Bl += (size_t)nb * sBn;
    bias += (size_t)nb * sBiasN;
    const size_t coff = (size_t)nb * sCn;
    const int bm = blockIdx.y * BM, bn = blockIdx.x * BN;

    const int lane = tid & 31, wid = tid >> 5;
    const int wm = wid & 3, wn = wid >> 2;       // warp grid 4(m) x 2(n)
    const int lr = lane & 15, lc = lane >> 4;

    float acc[2][8][4];
#pragma unroll
    for (int a = 0; a < 2; a++)
#pragma unroll
        for (int b = 0; b < 8; b++)
#pragma unroll
            for (int c = 0; c < 4; c++) acc[a][b][c] = 0.f;

    const int nk = K / BK;
    // preload 3 chunks
#pragma unroll
    for (int j = 0; j < 3; j++) {
        if (j < nk)
            load_chunk(sbase + j * STAGEB, tid, j * BK, Ah, Al, lda, bm, Bh, Bl, ldb, bn);
        CP_COMMIT();
    }

    for (int i = 0; i < nk; i++) {
        CP_WAIT2();
        __syncthreads();
        const uint32_t sb = sbase + (uint32_t)(i & 3) * STAGEB;

#pragma unroll
        for (int ks = 0; ks < 2; ks++) {
            const uint32_t koff = (uint32_t)(ks * 16 + lc * 8) * 2;
            uint32_t ah[2][4], al[2][4];
#pragma unroll
            for (int mt = 0; mt < 2; mt++) {
                uint32_t ra = sb + (uint32_t)(wm * 32 + mt * 16 + lr) * (RS * 2) + koff;
                LDSM4(ah[mt], ra);
                LDSM4(al[mt], ra + TILEB);
            }
#pragma unroll
            for (int nt = 0; nt < 4; nt++) {
                uint32_t rb = sb + 2 * TILEB +
                              (uint32_t)(wn * 64 + nt * 16 + lr) * (RS * 2) + koff;
                uint32_t bh[4], bl[4];
                LDSM4(bh, rb);
                LDSM4(bl, rb + TILEB);
                // hi*hi (4 independent acc tiles)
#pragma unroll
                for (int mt = 0; mt < 2; mt++) {
                    mma16816(acc[mt][nt * 2 + 0], ah[mt], bh[0], bh[2]);
                    mma16816(acc[mt][nt * 2 + 1], ah[mt], bh[1], bh[3]);
                }
                // hi*lo
#pragma unroll
                for (int mt = 0; mt < 2; mt++) {
                    mma16816(acc[mt][nt * 2 + 0], ah[mt], bl[0], bl[2]);
                    mma16816(acc[mt][nt * 2 + 1], ah[mt], bl[1], bl[3]);
                }
                // lo*hi
#pragma unroll
                for (int mt = 0; mt < 2; mt++) {
                    mma16816(acc[mt][nt * 2 + 0], al[mt], bh[0], bh[2]);
                    mma16816(acc[mt][nt * 2 + 1], al[mt], bh[1], bh[3]);
                }
            }
        }

        int j = i + 3;
        if (j < nk)
            load_chunk(sbase + (uint32_t)(j & 3) * STAGEB, tid, j * BK,
                       Ah, Al, lda, bm, Bh, Bl, ldb, bn);
        CP_COMMIT();
    }

    // Epilogue
    const int rbase = bm + wm * 32 + (lane >> 2);
    const int cbase = bn + wn * 64 + (lane & 3) * 2;
#pragma unroll
    for (int mt = 0; mt < 2; mt++) {
#pragma unroll
        for (int t8 = 0; t8 < 8; t8++) {
            const int r = rbase + mt * 16;
            const int c = cbase + t8 * 8;
            const float b0 = bias[c], b1 = bias[c + 1];
            float v00 = acc[mt][t8][0] + b0, v01 = acc[mt][t8][1] + b1;
            float v10 = acc[mt][t8][2] + b0, v11 = acc[mt][t8][3] + b1;
            if (ACT == 1) {
                v00 = v00 > 0.f ? v00 : expm1f(v00);
                v01 = v01 > 0.f ? v01 : expm1f(v01);
                v10 = v10 > 0.f ? v10 : expm1f(v10);
                v11 = v11 > 0.f ? v11 : expm1f(v11);
            }
            if (SPLIT) {
                __nv_bfloat16 h00 = __float2bfloat16(v00);
                __nv_bfloat16 h01 = __float2bfloat16(v01);
                __nv_bfloat16 h10 = __float2bfloat16(v10);
                __nv_bfloat16 h11 = __float2bfloat16(v11);
                float l00 = v00 - __bfloat162float(h00);
                float l01 = v01 - __bfloat162float(h01);
                float l10 = v10 - __bfloat162float(h10);
                float l11 = v11 - __bfloat162float(h11);
                __nv_bfloat162 H0 = {h00, h01}, H1 = {h10, h11};
                *(uint32_t*)(Ch + coff + (size_t)r * ldc + c) =
                    *reinterpret_cast<uint32_t*>(&H0);
                *(uint32_t*)(Ch + coff + (size_t)(r + 8) * ldc + c) =
                    *reinterpret_cast<uint32_t*>(&H1);
                *(uint32_t*)(Cl + coff + (size_t)r * ldc + c) = pack2bf16(l00, l01);
                *(uint32_t*)(Cl + coff + (size_t)(r + 8) * ldc + c) = pack2bf16(l10, l11);
            } else {
                *(float2*)(Cf + coff + (size_t)r * ldc + c) = make_float2(v00, v01);
                *(float2*)(Cf + coff + (size_t)(r + 8) * ldc + c) = make_float2(v10, v11);
            }
        }
    }
}

// ---------------- split fp32 -> bf16 hi/lo ---------------------------------
__global__ __launch_bounds__(256)
void split_k(const float* __restrict__ src, __nv_bfloat16* __restrict__ hi,
             __nv_bfloat16* __restrict__ lo, size_t n)
{
    size_t i = ((size_t)blockIdx.x * blockDim.x + threadIdx.x) * 4;
    if (i >= n) return;
    float4 v = *(const float4*)(src + i);
    float vv[4] = {v.x, v.y, v.z, v.w};
    unsigned short hs[4], ls[4];
#pragma unroll
    for (int j = 0; j < 4; j++) {
        __nv_bfloat16 h = __float2bfloat16(vv[j]);
        float r = vv[j] - __bfloat162float(h);
        __nv_bfloat16 l = __float2bfloat16(r);
        hs[j] = *reinterpret_cast<unsigned short*>(&h);
        ls[j] = *reinterpret_cast<unsigned short*>(&l);
    }
    *(uint2*)((unsigned short*)hi + i) = *(uint2*)hs;
    *(uint2*)((unsigned short*)lo + i) = *(uint2*)ls;
}

// ---------------- transpose + split: W[k][n] -> Wt_hi/lo[n][k] -------------
__global__ __launch_bounds__(256)
void tsplit_k(const float* __restrict__ src, __nv_bfloat16* __restrict__ hi,
              __nv_bfloat16* __restrict__ lo, int K, int Ncol)
{
    __shared__ float t[32][33];
    const size_t zoff = (size_t)blockIdx.z * K * Ncol;
    src += zoff; hi += zoff; lo += zoff;
    int k0 = blockIdx.y * 32, n0 = blockIdx.x * 32;
#pragma unroll
    for (int r = 0; r < 4; r++)
        t[threadIdx.y + r * 8][threadIdx.x] =
            src[(size_t)(k0 + threadIdx.y + r * 8) * Ncol + n0 + threadIdx.x];
    __syncthreads();
#pragma unroll
    for (int r = 0; r < 4; r++) {
        int n = n0 + threadIdx.y + r * 8;
        int k = k0 + threadIdx.x;
        float v = t[threadIdx.x][threadIdx.y + r * 8];
        __nv_bfloat16 h = __float2bfloat16(v);
        float rr = v - __bfloat162float(h);
        hi[(size_t)n * K + k] = h;
        lo[(size_t)n * K + k] = __float2bfloat16(rr);
    }
}

// ---------------- GLU elementwise ------------------------------------------
__global__ void glu_k(float* __restrict__ a, const float* __restrict__ b, size_t n)
{
    size_t i = (size_t)blockIdx.x * blockDim.x + threadIdx.x;
    if (i < n) {
        float s = 1.f / (1.f + expf(-a[i]));
        a[i] = s * b[i];
    }
}

// ---------------- LN(4096) + softmax over variable axis --------------------
__global__ __launch_bounds__(256)
void ln_softmax_k(const float* __restrict__ x, const float* __restrict__ g,
                  const float* __restrict__ gamma, const float* __restrict__ beta,
                  float* __restrict__ w)
{
    __shared__ float s[FEAT];
    __shared__ float red[8];
    const int b = blockIdx.x, t = threadIdx.x;
    const int lane = t & 31, wid = t >> 5;
    const float* xb = x + (size_t)b * FEAT;
    const float* gb = g + (size_t)b * FEAT;

    float lsum = 0.f;
    for (int i = t; i < FEAT; i += 256) {
        float v = xb[i] + gb[i];
        s[i] = v; lsum += v;
    }
#pragma unroll
    for (int o = 16; o; o >>= 1) lsum += __shfl_xor_sync(0xffffffff, lsum, o);
    if (lane == 0) red[wid] = lsum;
    __syncthreads();
    float tot = 0.f;
#pragma unroll
    for (int i = 0; i < 8; i++) tot += red[i];
    float mean = tot * (1.f / FEAT);
    __syncthreads();

    float lvar = 0.f;
    for (int i = t; i < FEAT; i += 256) { float d = s[i] - mean; lvar += d * d; }
#pragma unroll
    for (int o = 16; o; o >>= 1) lvar += __shfl_xor_sync(0xffffffff, lvar, o);
    if (lane == 0) red[wid] = lvar;
    __syncthreads();
    float vtot = 0.f;
#pragma unroll
    for (int i = 0; i < 8; i++) vtot += red[i];
    float rstd = rsqrtf(vtot * (1.f / FEAT) + 1e-5f);

    for (int i = t; i < FEAT; i += 256)
        s[i] = (s[i] - mean) * rstd * gamma[i] + beta[i];
    __syncthreads();

    float c[NVAR];
    float m = -1e30f;
#pragma unroll
    for (int n = 0; n < NVAR; n++) { c[n] = s[n * DDIM + t]; m = fmaxf(m, c[n]); }
    float sum = 0.f;
#pragma unroll
    for (int n = 0; n < NVAR; n++) { c[n] = expf(c[n] - m); sum += c[n]; }
    float inv = 1.f / sum;
    float* wb = w + (size_t)b * FEAT;
#pragma unroll
    for (int n = 0; n < NVAR; n++) wb[n * DDIM + t] = c[n] * inv;
}

// ---------------- per-(b,n) LN(256) + weighted combine ---------------------
__global__ __launch_bounds__(256)
void combine_k(const float* __restrict__ x, const float* __restrict__ gv,
               const float* __restrict__ w, const float* __restrict__ vlng,
               const float* __restrict__ vlnb, float* __restrict__ out)
{
    __shared__ float red[8];
    const int b = blockIdx.x, t = threadIdx.x;
    const int lane = t & 31, wid = t >> 5;

    float acc = 0.f;
    for (int n = 0; n < NVAR; n++) {
        size_t idx = (size_t)b * FEAT + n * DDIM + t;
        float v = x[idx] + gv[idx];
        float s1 = v;
#pragma unroll
        for (int o = 16; o; o >>= 1) s1 += __shfl_xor_sync(0xffffffff, s1, o);
        __syncthreads();
        if (lane == 0) red[wid] = s1;
        __syncthreads();
        float tot = 0.f;
#pragma unroll
        for (int i = 0; i < 8; i++) tot += red[i];
        float mean = tot * (1.f / DDIM);

        float d = v - mean;
        float s2 = d * d;
#pragma unroll
        for (int o = 16; o; o >>= 1) s2 += __shfl_xor_sync(0xffffffff, s2, o);
        __syncthreads();
        if (lane == 0) red[wid] = s2;
        __syncthreads();
        float vtot = 0.f;
#pragma unroll
        for (int i = 0; i < 8; i++) vtot += red[i];
        float rstd = rsqrtf(vtot * (1.f / DDIM) + 1e-5f);

        float yv = d * rstd * vlng[n * DDIM + t] + vlnb[n * DDIM + t];
        acc += w[idx] * yv;
    }
    out[(size_t)b * DDIM + t] = acc;
}

// ---------------- launch ----------------------------------------------------
extern "C" void kernel_launch(void* const* d_in, const int* in_sizes, int n_in,
                              void* d_out, int out_size)
{
    const float* x    = (const float*)d_in[0];
    const float* vW2  = (const float*)d_in[1];
    const float* vb2  = (const float*)d_in[2];
    const float* vW1  = (const float*)d_in[3];
    const float* vb1  = (const float*)d_in[4];
    const float* vW4  = (const float*)d_in[5];
    const float* vb4  = (const float*)d_in[6];
    const float* vW5  = (const float*)d_in[7];
    const float* vb5  = (const float*)d_in[8];
    const float* vlng = (const float*)d_in[9];
    const float* vlnb = (const float*)d_in[10];
    const float* cW2  = (const float*)d_in[11];
    const float* cb2  = (const float*)d_in[12];
    const float* cW1  = (const float*)d_in[13];
    const float* cb1  = (const float*)d_in[14];
    const float* cW4  = (const float*)d_in[15];
    const float* cb4  = (const float*)d_in[16];
    const float* cW5  = (const float*)d_in[17];
    const float* cb5  = (const float*)d_in[18];
    const float* clng = (const float*)d_in[19];
    const float* clnb = (const float*)d_in[20];
    float* out = (float*)d_out;

    float *buf0, *buf1, *buf2, *buf3;
    cudaGetSymbolAddress((void**)&buf0, g_buf0);
    cudaGetSymbolAddress((void**)&buf1, g_buf1);
    cudaGetSymbolAddress((void**)&buf2, g_buf2);
    cudaGetSymbolAddress((void**)&buf3, g_buf3);
    __nv_bfloat16 *xh, *xl, *hh, *hl, *eh, *el;
    cudaGetSymbolAddress((void**)&xh, g_xh); cudaGetSymbolAddress((void**)&xl, g_xl);
    cudaGetSymbolAddress((void**)&hh, g_hh); cudaGetSymbolAddress((void**)&hl, g_hl);
    cudaGetSymbolAddress((void**)&eh, g_eh); cudaGetSymbolAddress((void**)&el, g_el);
    __nv_bfloat16 *cW2h, *cW2l, *cW1h, *cW1l, *cW4h, *cW4l, *cW5h, *cW5l;
    cudaGetSymbolAddress((void**)&cW2h, g_cW2h); cudaGetSymbolAddress((void**)&cW2l, g_cW2l);
    cudaGetSymbolAddress((void**)&cW1h, g_cW1h); cudaGetSymbolAddress((void**)&cW1l, g_cW1l);
    cudaGetSymbolAddress((void**)&cW4h, g_cW4h); cudaGetSymbolAddress((void**)&cW4l, g_cW4l);
    cudaGetSymbolAddress((void**)&cW5h, g_cW5h); cudaGetSymbolAddress((void**)&cW5l, g_cW5l);
    __nv_bfloat16 *vW2h, *vW2l, *vW1h, *vW1l, *vW4h, *vW4l, *vW5h, *vW5l;
    cudaGetSymbolAddress((void**)&vW2h, g_vW2h); cudaGetSymbolAddress((void**)&vW2l, g_vW2l);
    cudaGetSymbolAddress((void**)&vW1h, g_vW1h); cudaGetSymbolAddress((void**)&vW1l, g_vW1l);
    cudaGetSymbolAddress((void**)&vW4h, g_vW4h); cudaGetSymbolAddress((void**)&vW4l, g_vW4l);
    cudaGetSymbolAddress((void**)&vW5h, g_vW5h); cudaGetSymbolAddress((void**)&vW5l, g_vW5l);

    cudaFuncSetAttribute(tgemm_k<1, 1>, cudaFuncAttributeMaxDynamicSharedMemorySize, GEMM_SMEM);
    cudaFuncSetAttribute(tgemm_k<0, 1>, cudaFuncAttributeMaxDynamicSharedMemorySize, GEMM_SMEM);
    cudaFuncSetAttribute(tgemm_k<0, 0>, cudaFuncAttributeMaxDynamicSharedMemorySize, GEMM_SMEM);

    const size_t NE = NELEM;

    // ---- conversions ----
    split_k<<<(unsigned)(NE / 1024), 256>>>(x, xh, xl, NE);
    {
        dim3 g(128, 128, 1), b(32, 8);
        tsplit_k<<<g, b>>>(cW2, cW2h, cW2l, FEAT, FEAT);
        tsplit_k<<<g, b>>>(cW1, cW1h, cW1l, FEAT, FEAT);
        tsplit_k<<<g, b>>>(cW4, cW4h, cW4l, FEAT, FEAT);
        tsplit_k<<<g, b>>>(cW5, cW5h, cW5l, FEAT, FEAT);
        dim3 gv(8, 8, NVAR);
        tsplit_k<<<gv, b>>>(vW2, vW2h, vW2l, DDIM, DDIM);
        tsplit_k<<<gv, b>>>(vW1, vW1h, vW1l, DDIM, DDIM);
        tsplit_k<<<gv, b>>>(vW4, vW4h, vW4l, DDIM, DDIM);
        tsplit_k<<<gv, b>>>(vW5, vW5h, vW5l, DDIM, DDIM);
    }

    dim3 gridC(FEAT / BN, BATCH / BM, 1);     // 32 x 32
    dim3 gridV(DDIM / BN, BATCH / BM, NVAR);  // 2 x 32 x 16
    dim3 blk(256);

    // ---- concat GRN ----
    tgemm_k<1, 1><<<gridC, blk, GEMM_SMEM>>>(xh, xl, FEAT, 0, cW2h, cW2l, FEAT, 0,
                                             cb2, 0, nullptr, hh, hl, FEAT, 0, FEAT);
    tgemm_k<0, 1><<<gridC, blk, GEMM_SMEM>>>(hh, hl, FEAT, 0, cW1h, cW1l, FEAT, 0,
                                             cb1, 0, nullptr, eh, el, FEAT, 0, FEAT);
    tgemm_k<0, 0><<<gridC, blk, GEMM_SMEM>>>(eh, el, FEAT, 0, cW4h, cW4l, FEAT, 0,
                                             cb4, 0, buf0, nullptr, nullptr, FEAT, 0, FEAT);
    tgemm_k<0, 0><<<gridC, blk, GEMM_SMEM>>>(eh, el, FEAT, 0, cW5h, cW5l, FEAT, 0,
                                             cb5, 0, buf1, nullptr, nullptr, FEAT, 0, FEAT);
    glu_k<<<(unsigned)(NE / 256), 256>>>(buf0, buf1, NE);
    ln_softmax_k<<<BATCH, 256>>>(x, buf0, clng, clnb, buf1);   // weights -> buf1

    // ---- per-variable GRNs ----
    tgemm_k<1, 1><<<gridV, blk, GEMM_SMEM>>>(xh, xl, FEAT, DDIM, vW2h, vW2l, DDIM,
                                             (long)DDIM * DDIM, vb2, DDIM,
                                             nullptr, hh, hl, FEAT, DDIM, DDIM);
    tgemm_k<0, 1><<<gridV, blk, GEMM_SMEM>>>(hh, hl, FEAT, DDIM, vW1h, vW1l, DDIM,
                                             (long)DDIM * DDIM, vb1, DDIM,
                                             nullptr, eh, el, FEAT, DDIM, DDIM);
    tgemm_k<0, 0><<<gridV, blk, GEMM_SMEM>>>(eh, el, FEAT, DDIM, vW4h, vW4l, DDIM,
                                             (long)DDIM * DDIM, vb4, DDIM,
                                             buf2, nullptr, nullptr, FEAT, DDIM, DDIM);
    tgemm_k<0, 0><<<gridV, blk, GEMM_SMEM>>>(eh, el, FEAT, DDIM, vW5h, vW5l, DDIM,
                                             (long)DDIM * DDIM, vb5, DDIM,
                                             buf3, nullptr, nullptr, FEAT, DDIM, DDIM);
    glu_k<<<(unsigned)(NE / 256), 256>>>(buf2, buf3, NE);

    combine_k<<<BATCH, 256>>>(x, buf2, buf1, vlng, vlnb, out);
}

// round 5
// speedup vs baseline: 2.2123x; 1.0015x over previous
#include <cuda_runtime.h>
#include <cuda_bf16.h>
#include <math.h>
#include <stdint.h>

#define BATCH 4096
#define NVAR  16
#define DDIM  256
#define FEAT  4096
#define NELEM ((size_t)BATCH * FEAT)     // 16,777,216
#define VWN   ((size_t)NVAR * DDIM * DDIM)

// ---------------- scratch (device globals; allocation forbidden) -----------
__device__ __align__(256) float g_buf0[NELEM];
__device__ __align__(256) float g_buf1[NELEM];
__device__ __align__(256) float g_buf2[NELEM];
__device__ __align__(256) float g_buf3[NELEM];
__device__ __align__(256) __nv_bfloat16 g_xh[NELEM], g_xl[NELEM];
__device__ __align__(256) __nv_bfloat16 g_hh[NELEM], g_hl[NELEM];
__device__ __align__(256) __nv_bfloat16 g_eh[NELEM], g_el[NELEM];
__device__ __align__(256) __nv_bfloat16 g_cW2h[NELEM], g_cW2l[NELEM];
__device__ __align__(256) __nv_bfloat16 g_cW1h[NELEM], g_cW1l[NELEM];
__device__ __align__(256) __nv_bfloat16 g_cW4h[NELEM], g_cW4l[NELEM];
__device__ __align__(256) __nv_bfloat16 g_cW5h[NELEM], g_cW5l[NELEM];
__device__ __align__(256) __nv_bfloat16 g_vW2h[VWN], g_vW2l[VWN];
__device__ __align__(256) __nv_bfloat16 g_vW1h[VWN], g_vW1l[VWN];
__device__ __align__(256) __nv_bfloat16 g_vW4h[VWN], g_vW4l[VWN];
__device__ __align__(256) __nv_bfloat16 g_vW5h[VWN], g_vW5l[VWN];

// ---------------- helpers ---------------------------------------------------
__device__ __forceinline__ uint32_t smem_u32(const void* p) {
    uint32_t a;
    asm("{ .reg .u64 t; cvta.to.shared.u64 t, %1; cvt.u32.u64 %0, t; }"
        : "=r"(a) : "l"(p));
    return a;
}

#define CP_ASYNC16(dst, src) \
    asm volatile("cp.async.cg.shared.global [%0], [%1], 16;" :: "r"(dst), "l"(src))
#define CP_COMMIT() asm volatile("cp.async.commit_group;" ::: "memory")
#define CP_WAIT2()  asm volatile("cp.async.wait_group 2;" ::: "memory")

#define LDSM4(r, a) \
    asm volatile("ldmatrix.sync.aligned.m8n8.x4.shared.b16 {%0,%1,%2,%3}, [%4];" \
                 : "=r"((r)[0]), "=r"((r)[1]), "=r"((r)[2]), "=r"((r)[3]) : "r"(a))

__device__ __forceinline__ void mma16816(float* d, const uint32_t* a,
                                         uint32_t b0, uint32_t b1) {
    asm volatile(
        "mma.sync.aligned.m16n8k16.row.col.f32.bf16.bf16.f32 "
        "{%0,%1,%2,%3}, {%4,%5,%6,%7}, {%8,%9}, {%0,%1,%2,%3};"
        : "+f"(d[0]), "+f"(d[1]), "+f"(d[2]), "+f"(d[3])
        : "r"(a[0]), "r"(a[1]), "r"(a[2]), "r"(a[3]), "r"(b0), "r"(b1));
}

__device__ __forceinline__ uint32_t pack2bf16(float v0, float v1) {
    __nv_bfloat162 t = __floats2bfloat162_rn(v0, v1);
    return *reinterpret_cast<uint32_t*>(&t);
}

// ---------------- GEMM (mma.sync bf16, 3-product split) --------------------
// BM=BN=128, BK=32, 256 threads, 4-stage cp.async pipeline.
#define BM 128
#define BN 128
#define BK 32
#define RS 40                           // smem row stride in bf16 elems (80 B)
#define TILEB (128 * RS * 2)            // 10240 B per (matrix, hi|lo) tile
#define STAGEB (4 * TILEB)              // 40960 B per stage
#define NSTAGE 4
#define GEMM_SMEM (NSTAGE * STAGEB)     // 163840 B

__device__ __forceinline__ void load_chunk(
    uint32_t s0, int tid, int k0,
    const __nv_bfloat16* __restrict__ Ah, const __nv_bfloat16* __restrict__ Al,
    int lda, int bm,
    const __nv_bfloat16* __restrict__ Bh, const __nv_bfloat16* __restrict__ Bl,
    int ldb, int bn)
{
#pragma unroll
    for (int r = 0; r < 2; r++) {
        int e = tid + r * 256;
        int row = e >> 2, seg = e & 3;
        uint32_t off = (uint32_t)row * (RS * 2) + seg * 16;
        size_t ga = (size_t)(bm + row) * lda + k0 + seg * 8;
        size_t gb = (size_t)(bn + row) * ldb + k0 + seg * 8;
        CP_ASYNC16(s0 + off,             Ah + ga);
        CP_ASYNC16(s0 + TILEB + off,     Al + ga);
        CP_ASYNC16(s0 + 2 * TILEB + off, Bh + gb);
        CP_ASYNC16(s0 + 3 * TILEB + off, Bl + gb);
    }
}

// ACT: 0 none, 1 ELU.  SPLIT: 1 -> write bf16 hi/lo, 0 -> write fp32.
template <int ACT, int SPLIT>
__global__ __launch_bounds__(256, 1)
void tgemm_k(const __nv_bfloat16* __restrict__ Ah, const __nv_bfloat16* __restrict__ Al,
             int lda, long sAn,
             const __nv_bfloat16* __restrict__ Bh, const __nv_bfloat16* __restrict__ Bl,
             int ldb, long sBn,
             const float* __restrict__ bias, int sBiasN,
             float* __restrict__ Cf, __nv_bfloat16* __restrict__ Ch,
             __nv_bfloat16* __restrict__ Cl, int ldc, long sCn,
             int K)
{
    extern __shared__ char smem[];
    const uint32_t sbase = smem_u32(smem);
    const int tid = threadIdx.x;
    const int nb = blockIdx.z;
    Ah += (size_t)nb * sAn;  Al += (size_t)nb * sAn;
    Bh += (size_t)nb * sBn;  Bl += (size_t)nb * sBn;
    bias += (size_t)nb * sBiasN;
    const size_t coff = (size_t)nb * sCn;
    const int bm = blockIdx.y * BM, bn = blockIdx.x * BN;

    const int lane = tid & 31, wid = tid >> 5;
    const int wm = wid & 3, wn = wid >> 2;       // warp grid 4(m) x 2(n)
    const int lr = lane & 15, lc = lane >> 4;

    float acc[2][8][4];
#pragma unroll
    for (int a = 0; a < 2; a++)
#pragma unroll
        for (int b = 0; b < 8; b++)
#pragma unroll
            for (int c = 0; c < 4; c++) acc[a][b][c] = 0.f;

    const int nk = K / BK;
    // preload 3 chunks
#pragma unroll
    for (int j = 0; j < 3; j++) {
        if (j < nk)
            load_chunk(sbase + j * STAGEB, tid, j * BK, Ah, Al, lda, bm, Bh, Bl, ldb, bn);
        CP_COMMIT();
    }

    for (int i = 0; i < nk; i++) {
        CP_WAIT2();
        __syncthreads();
        const uint32_t sb = sbase + (uint32_t)(i & 3) * STAGEB;

#pragma unroll
        for (int ks = 0; ks < 2; ks++) {
            const uint32_t koff = (uint32_t)(ks * 16 + lc * 8) * 2;
            uint32_t ah[2][4], al[2][4];
#pragma unroll
            for (int mt = 0; mt < 2; mt++) {
                uint32_t ra = sb + (uint32_t)(wm * 32 + mt * 16 + lr) * (RS * 2) + koff;
                LDSM4(ah[mt], ra);
                LDSM4(al[mt], ra + TILEB);
            }
#pragma unroll
            for (int nt = 0; nt < 4; nt++) {
                uint32_t rb = sb + 2 * TILEB +
                              (uint32_t)(wn * 64 + nt * 16 + lr) * (RS * 2) + koff;
                uint32_t bh[4], bl[4];
                LDSM4(bh, rb);
                LDSM4(bl, rb + TILEB);
                // hi*hi (4 independent acc tiles)
#pragma unroll
                for (int mt = 0; mt < 2; mt++) {
                    mma16816(acc[mt][nt * 2 + 0], ah[mt], bh[0], bh[2]);
                    mma16816(acc[mt][nt * 2 + 1], ah[mt], bh[1], bh[3]);
                }
                // hi*lo
#pragma unroll
                for (int mt = 0; mt < 2; mt++) {
                    mma16816(acc[mt][nt * 2 + 0], ah[mt], bl[0], bl[2]);
                    mma16816(acc[mt][nt * 2 + 1], ah[mt], bl[1], bl[3]);
                }
                // lo*hi
#pragma unroll
                for (int mt = 0; mt < 2; mt++) {
                    mma16816(acc[mt][nt * 2 + 0], al[mt], bh[0], bh[2]);
                    mma16816(acc[mt][nt * 2 + 1], al[mt], bh[1], bh[3]);
                }
            }
        }

        int j = i + 3;
        if (j < nk)
            load_chunk(sbase + (uint32_t)(j & 3) * STAGEB, tid, j * BK,
                       Ah, Al, lda, bm, Bh, Bl, ldb, bn);
        CP_COMMIT();
    }

    // Epilogue
    const int rbase = bm + wm * 32 + (lane >> 2);
    const int cbase = bn + wn * 64 + (lane & 3) * 2;
#pragma unroll
    for (int mt = 0; mt < 2; mt++) {
#pragma unroll
        for (int t8 = 0; t8 < 8; t8++) {
            const int r = rbase + mt * 16;
            const int c = cbase + t8 * 8;
            const float b0 = bias[c], b1 = bias[c + 1];
            float v00 = acc[mt][t8][0] + b0, v01 = acc[mt][t8][1] + b1;
            float v10 = acc[mt][t8][2] + b0, v11 = acc[mt][t8][3] + b1;
            if (ACT == 1) {
                v00 = v00 > 0.f ? v00 : expm1f(v00);
                v01 = v01 > 0.f ? v01 : expm1f(v01);
                v10 = v10 > 0.f ? v10 : expm1f(v10);
                v11 = v11 > 0.f ? v11 : expm1f(v11);
            }
            if (SPLIT) {
                __nv_bfloat16 h00 = __float2bfloat16(v00);
                __nv_bfloat16 h01 = __float2bfloat16(v01);
                __nv_bfloat16 h10 = __float2bfloat16(v10);
                __nv_bfloat16 h11 = __float2bfloat16(v11);
                float l00 = v00 - __bfloat162float(h00);
                float l01 = v01 - __bfloat162float(h01);
                float l10 = v10 - __bfloat162float(h10);
                float l11 = v11 - __bfloat162float(h11);
                __nv_bfloat162 H0 = {h00, h01}, H1 = {h10, h11};
                *(uint32_t*)(Ch + coff + (size_t)r * ldc + c) =
                    *reinterpret_cast<uint32_t*>(&H0);
                *(uint32_t*)(Ch + coff + (size_t)(r + 8) * ldc + c) =
                    *reinterpret_cast<uint32_t*>(&H1);
                *(uint32_t*)(Cl + coff + (size_t)r * ldc + c) = pack2bf16(l00, l01);
                *(uint32_t*)(Cl + coff + (size_t)(r + 8) * ldc + c) = pack2bf16(l10, l11);
            } else {
                *(float2*)(Cf + coff + (size_t)r * ldc + c) = make_float2(v00, v01);
                *(float2*)(Cf + coff + (size_t)(r + 8) * ldc + c) = make_float2(v10, v11);
            }
        }
    }
}

// ---------------- split fp32 -> bf16 hi/lo ---------------------------------
__global__ __launch_bounds__(256)
void split_k(const float* __restrict__ src, __nv_bfloat16* __restrict__ hi,
             __nv_bfloat16* __restrict__ lo, size_t n)
{
    size_t i = ((size_t)blockIdx.x * blockDim.x + threadIdx.x) * 4;
    if (i >= n) return;
    float4 v = *(const float4*)(src + i);
    float vv[4] = {v.x, v.y, v.z, v.w};
    unsigned short hs[4], ls[4];
#pragma unroll
    for (int j = 0; j < 4; j++) {
        __nv_bfloat16 h = __float2bfloat16(vv[j]);
        float r = vv[j] - __bfloat162float(h);
        __nv_bfloat16 l = __float2bfloat16(r);
        hs[j] = *reinterpret_cast<unsigned short*>(&h);
        ls[j] = *reinterpret_cast<unsigned short*>(&l);
    }
    *(uint2*)((unsigned short*)hi + i) = *(uint2*)hs;
    *(uint2*)((unsigned short*)lo + i) = *(uint2*)ls;
}

// ---------------- transpose + split: W[k][n] -> Wt_hi/lo[n][k] -------------
__global__ __launch_bounds__(256)
void tsplit_k(const float* __restrict__ src, __nv_bfloat16* __restrict__ hi,
              __nv_bfloat16* __restrict__ lo, int K, int Ncol)
{
    __shared__ float t[32][33];
    const size_t zoff = (size_t)blockIdx.z * K * Ncol;
    src += zoff; hi += zoff; lo += zoff;
    int k0 = blockIdx.y * 32, n0 = blockIdx.x * 32;
#pragma unroll
    for (int r = 0; r < 4; r++)
        t[threadIdx.y + r * 8][threadIdx.x] =
            src[(size_t)(k0 + threadIdx.y + r * 8) * Ncol + n0 + threadIdx.x];
    __syncthreads();
#pragma unroll
    for (int r = 0; r < 4; r++) {
        int n = n0 + threadIdx.y + r * 8;
        int k = k0 + threadIdx.x;
        float v = t[threadIdx.x][threadIdx.y + r * 8];
        __nv_bfloat16 h = __float2bfloat16(v);
        float rr = v - __bfloat162float(h);
        hi[(size_t)n * K + k] = h;
        lo[(size_t)n * K + k] = __float2bfloat16(rr);
    }
}

// ---------------- GLU elementwise ------------------------------------------
__global__ void glu_k(float* __restrict__ a, const float* __restrict__ b, size_t n)
{
    size_t i = (size_t)blockIdx.x * blockDim.x + threadIdx.x;
    if (i < n) {
        float s = 1.f / (1.f + expf(-a[i]));
        a[i] = s * b[i];
    }
}

// ---------------- LN(4096) + softmax over variable axis --------------------
__global__ __launch_bounds__(256)
void ln_softmax_k(const float* __restrict__ x, const float* __restrict__ g,
                  const float* __restrict__ gamma, const float* __restrict__ beta,
                  float* __restrict__ w)
{
    __shared__ float s[FEAT];
    __shared__ float red[8];
    const int b = blockIdx.x, t = threadIdx.x;
    const int lane = t & 31, wid = t >> 5;
    const float* xb = x + (size_t)b * FEAT;
    const float* gb = g + (size_t)b * FEAT;

    float lsum = 0.f;
    for (int i = t; i < FEAT; i += 256) {
        float v = xb[i] + gb[i];
        s[i] = v; lsum += v;
    }
#pragma unroll
    for (int o = 16; o; o >>= 1) lsum += __shfl_xor_sync(0xffffffff, lsum, o);
    if (lane == 0) red[wid] = lsum;
    __syncthreads();
    float tot = 0.f;
#pragma unroll
    for (int i = 0; i < 8; i++) tot += red[i];
    float mean = tot * (1.f / FEAT);
    __syncthreads();

    float lvar = 0.f;
    for (int i = t; i < FEAT; i += 256) { float d = s[i] - mean; lvar += d * d; }
#pragma unroll
    for (int o = 16; o; o >>= 1) lvar += __shfl_xor_sync(0xffffffff, lvar, o);
    if (lane == 0) red[wid] = lvar;
    __syncthreads();
    float vtot = 0.f;
#pragma unroll
    for (int i = 0; i < 8; i++) vtot += red[i];
    float rstd = rsqrtf(vtot * (1.f / FEAT) + 1e-5f);

    for (int i = t; i < FEAT; i += 256)
        s[i] = (s[i] - mean) * rstd * gamma[i] + beta[i];
    __syncthreads();

    float c[NVAR];
    float m = -1e30f;
#pragma unroll
    for (int n = 0; n < NVAR; n++) { c[n] = s[n * DDIM + t]; m = fmaxf(m, c[n]); }
    float sum = 0.f;
#pragma unroll
    for (int n = 0; n < NVAR; n++) { c[n] = expf(c[n] - m); sum += c[n]; }
    float inv = 1.f / sum;
    float* wb = w + (size_t)b * FEAT;
#pragma unroll
    for (int n = 0; n < NVAR; n++) wb[n * DDIM + t] = c[n] * inv;
}

// ---------------- per-(b,n) LN(256) + weighted combine ---------------------
__global__ __launch_bounds__(256)
void combine_k(const float* __restrict__ x, const float* __restrict__ gv,
               const float* __restrict__ w, const float* __restrict__ vlng,
               const float* __restrict__ vlnb, float* __restrict__ out)
{
    __shared__ float red[8];
    const int b = blockIdx.x, t = threadIdx.x;
    const int lane = t & 31, wid = t >> 5;

    float acc = 0.f;
    for (int n = 0; n < NVAR; n++) {
        size_t idx = (size_t)b * FEAT + n * DDIM + t;
        float v = x[idx] + gv[idx];
        float s1 = v;
#pragma unroll
        for (int o = 16; o; o >>= 1) s1 += __shfl_xor_sync(0xffffffff, s1, o);
        __syncthreads();
        if (lane == 0) red[wid] = s1;
        __syncthreads();
        float tot = 0.f;
#pragma unroll
        for (int i = 0; i < 8; i++) tot += red[i];
        float mean = tot * (1.f / DDIM);

        float d = v - mean;
        float s2 = d * d;
#pragma unroll
        for (int o = 16; o; o >>= 1) s2 += __shfl_xor_sync(0xffffffff, s2, o);
        __syncthreads();
        if (lane == 0) red[wid] = s2;
        __syncthreads();
        float vtot = 0.f;
#pragma unroll
        for (int i = 0; i < 8; i++) vtot += red[i];
        float rstd = rsqrtf(vtot * (1.f / DDIM) + 1e-5f);

        float yv = d * rstd * vlng[n * DDIM + t] + vlnb[n * DDIM + t];
        acc += w[idx] * yv;
    }
    out[(size_t)b * DDIM + t] = acc;
}

// ---------------- launch ----------------------------------------------------
extern "C" void kernel_launch(void* const* d_in, const int* in_sizes, int n_in,
                              void* d_out, int out_size)
{
    const float* x    = (const float*)d_in[0];
    const float* vW2  = (const float*)d_in[1];
    const float* vb2  = (const float*)d_in[2];
    const float* vW1  = (const float*)d_in[3];
    const float* vb1  = (const float*)d_in[4];
    const float* vW4  = (const float*)d_in[5];
    const float* vb4  = (const float*)d_in[6];
    const float* vW5  = (const float*)d_in[7];
    const float* vb5  = (const float*)d_in[8];
    const float* vlng = (const float*)d_in[9];
    const float* vlnb = (const float*)d_in[10];
    const float* cW2  = (const float*)d_in[11];
    const float* cb2  = (const float*)d_in[12];
    const float* cW1  = (const float*)d_in[13];
    const float* cb1  = (const float*)d_in[14];
    const float* cW4  = (const float*)d_in[15];
    const float* cb4  = (const float*)d_in[16];
    const float* cW5  = (const float*)d_in[17];
    const float* cb5  = (const float*)d_in[18];
    const float* clng = (const float*)d_in[19];
    const float* clnb = (const float*)d_in[20];
    float* out = (float*)d_out;

    float *buf0, *buf1, *buf2, *buf3;
    cudaGetSymbolAddress((void**)&buf0, g_buf0);
    cudaGetSymbolAddress((void**)&buf1, g_buf1);
    cudaGetSymbolAddress((void**)&buf2, g_buf2);
    cudaGetSymbolAddress((void**)&buf3, g_buf3);
    __nv_bfloat16 *xh, *xl, *hh, *hl, *eh, *el;
    cudaGetSymbolAddress((void**)&xh, g_xh); cudaGetSymbolAddress((void**)&xl, g_xl);
    cudaGetSymbolAddress((void**)&hh, g_hh); cudaGetSymbolAddress((void**)&hl, g_hl);
    cudaGetSymbolAddress((void**)&eh, g_eh); cudaGetSymbolAddress((void**)&el, g_el);
    __nv_bfloat16 *cW2h, *cW2l, *cW1h, *cW1l, *cW4h, *cW4l, *cW5h, *cW5l;
    cudaGetSymbolAddress((void**)&cW2h, g_cW2h); cudaGetSymbolAddress((void**)&cW2l, g_cW2l);
    cudaGetSymbolAddress((void**)&cW1h, g_cW1h); cudaGetSymbolAddress((void**)&cW1l, g_cW1l);
    cudaGetSymbolAddress((void**)&cW4h, g_cW4h); cudaGetSymbolAddress((void**)&cW4l, g_cW4l);
    cudaGetSymbolAddress((void**)&cW5h, g_cW5h); cudaGetSymbolAddress((void**)&cW5l, g_cW5l);
    __nv_bfloat16 *vW2h, *vW2l, *vW1h, *vW1l, *vW4h, *vW4l, *vW5h, *vW5l;
    cudaGetSymbolAddress((void**)&vW2h, g_vW2h); cudaGetSymbolAddress((void**)&vW2l, g_vW2l);
    cudaGetSymbolAddress((void**)&vW1h, g_vW1h); cudaGetSymbolAddress((void**)&vW1l, g_vW1l);
    cudaGetSymbolAddress((void**)&vW4h, g_vW4h); cudaGetSymbolAddress((void**)&vW4l, g_vW4l);
    cudaGetSymbolAddress((void**)&vW5h, g_vW5h); cudaGetSymbolAddress((void**)&vW5l, g_vW5l);

    cudaFuncSetAttribute(tgemm_k<1, 1>, cudaFuncAttributeMaxDynamicSharedMemorySize, GEMM_SMEM);
    cudaFuncSetAttribute(tgemm_k<0, 1>, cudaFuncAttributeMaxDynamicSharedMemorySize, GEMM_SMEM);
    cudaFuncSetAttribute(tgemm_k<0, 0>, cudaFuncAttributeMaxDynamicSharedMemorySize, GEMM_SMEM);

    const size_t NE = NELEM;

    // ---- conversions ----
    split_k<<<(unsigned)(NE / 1024), 256>>>(x, xh, xl, NE);
    {
        dim3 g(128, 128, 1), b(32, 8);
        tsplit_k<<<g, b>>>(cW2, cW2h, cW2l, FEAT, FEAT);
        tsplit_k<<<g, b>>>(cW1, cW1h, cW1l, FEAT, FEAT);
        tsplit_k<<<g, b>>>(cW4, cW4h, cW4l, FEAT, FEAT);
        tsplit_k<<<g, b>>>(cW5, cW5h, cW5l, FEAT, FEAT);
        dim3 gv(8, 8, NVAR);
        tsplit_k<<<gv, b>>>(vW2, vW2h, vW2l, DDIM, DDIM);
        tsplit_k<<<gv, b>>>(vW1, vW1h, vW1l, DDIM, DDIM);
        tsplit_k<<<gv, b>>>(vW4, vW4h, vW4l, DDIM, DDIM);
        tsplit_k<<<gv, b>>>(vW5, vW5h, vW5l, DDIM, DDIM);
    }

    dim3 gridC(FEAT / BN, BATCH / BM, 1);     // 32 x 32
    dim3 gridV(DDIM / BN, BATCH / BM, NVAR);  // 2 x 32 x 16
    dim3 blk(256);

    // ---- concat GRN ----
    tgemm_k<1, 1><<<gridC, blk, GEMM_SMEM>>>(xh, xl, FEAT, 0, cW2h, cW2l, FEAT, 0,
                                             cb2, 0, nullptr, hh, hl, FEAT, 0, FEAT);
    tgemm_k<0, 1><<<gridC, blk, GEMM_SMEM>>>(hh, hl, FEAT, 0, cW1h, cW1l, FEAT, 0,
                                             cb1, 0, nullptr, eh, el, FEAT, 0, FEAT);
    tgemm_k<0, 0><<<gridC, blk, GEMM_SMEM>>>(eh, el, FEAT, 0, cW4h, cW4l, FEAT, 0,
                                             cb4, 0, buf0, nullptr, nullptr, FEAT, 0, FEAT);
    tgemm_k<0, 0><<<gridC, blk, GEMM_SMEM>>>(eh, el, FEAT, 0, cW5h, cW5l, FEAT, 0,
                                             cb5, 0, buf1, nullptr, nullptr, FEAT, 0, FEAT);
    glu_k<<<(unsigned)(NE / 256), 256>>>(buf0, buf1, NE);
    ln_softmax_k<<<BATCH, 256>>>(x, buf0, clng, clnb, buf1);   // weights -> buf1

    // ---- per-variable GRNs ----
    tgemm_k<1, 1><<<gridV, blk, GEMM_SMEM>>>(xh, xl, FEAT, DDIM, vW2h, vW2l, DDIM,
                                             (long)DDIM * DDIM, vb2, DDIM,
                                             nullptr, hh, hl, FEAT, DDIM, DDIM);
    tgemm_k<0, 1><<<gridV, blk, GEMM_SMEM>>>(hh, hl, FEAT, DDIM, vW1h, vW1l, DDIM,
                                             (long)DDIM * DDIM, vb1, DDIM,
                                             nullptr, eh, el, FEAT, DDIM, DDIM);
    tgemm_k<0, 0><<<gridV, blk, GEMM_SMEM>>>(eh, el, FEAT, DDIM, vW4h, vW4l, DDIM,
                                             (long)DDIM * DDIM, vb4, DDIM,
                                             buf2, nullptr, nullptr, FEAT, DDIM, DDIM);
    tgemm_k<0, 0><<<gridV, blk, GEMM_SMEM>>>(eh, el, FEAT, DDIM, vW5h, vW5l, DDIM,
                                             (long)DDIM * DDIM, vb5, DDIM,
                                             buf3, nullptr, nullptr, FEAT, DDIM, DDIM);
    glu_k<<<(unsigned)(NE / 256), 256>>>(buf2, buf3, NE);

    combine_k<<<BATCH, 256>>>(x, buf2, buf1, vlng, vlnb, out);
}

// round 6
// speedup vs baseline: 3.1275x; 1.4137x over previous
#include <cuda_runtime.h>
#include <cuda_fp16.h>
#include <math.h>
#include <stdint.h>

#define BATCH 4096
#define NVAR  16
#define DDIM  256
#define FEAT  4096
#define NELEM ((size_t)BATCH * FEAT)     // 16,777,216
#define VWN   ((size_t)NVAR * DDIM * DDIM)

// ---------------- scratch (device globals; allocation forbidden) -----------
__device__ __align__(256) float g_buf0[NELEM];
__device__ __align__(256) float g_buf1[NELEM];
__device__ __align__(256) float g_buf2[NELEM];
__device__ __align__(256) float g_buf3[NELEM];
// fp16 activations (hi only)
__device__ __align__(256) __half g_xh[NELEM];
__device__ __align__(256) __half g_hh[NELEM];
__device__ __align__(256) __half g_eh[NELEM];
// transposed concat weights, fp16 hi/lo
__device__ __align__(256) __half g_cW2h[NELEM], g_cW2l[NELEM];
__device__ __align__(256) __half g_cW1h[NELEM], g_cW1l[NELEM];
__device__ __align__(256) __half g_cW4h[NELEM], g_cW4l[NELEM];
__device__ __align__(256) __half g_cW5h[NELEM], g_cW5l[NELEM];
// transposed per-variable weights, fp16 hi/lo
__device__ __align__(256) __half g_vW2h[VWN], g_vW2l[VWN];
__device__ __align__(256) __half g_vW1h[VWN], g_vW1l[VWN];
__device__ __align__(256) __half g_vW4h[VWN], g_vW4l[VWN];
__device__ __align__(256) __half g_vW5h[VWN], g_vW5l[VWN];

// ---------------- helpers ---------------------------------------------------
__device__ __forceinline__ uint32_t smem_u32(const void* p) {
    uint32_t a;
    asm("{ .reg .u64 t; cvta.to.shared.u64 t, %1; cvt.u32.u64 %0, t; }"
        : "=r"(a) : "l"(p));
    return a;
}

#define CP_ASYNC16(dst, src) \
    asm volatile("cp.async.cg.shared.global [%0], [%1], 16;" :: "r"(dst), "l"(src))
#define CP_COMMIT() asm volatile("cp.async.commit_group;" ::: "memory")
#define CP_WAIT2()  asm volatile("cp.async.wait_group 2;" ::: "memory")

#define LDSM4(r, a) \
    asm volatile("ldmatrix.sync.aligned.m8n8.x4.shared.b16 {%0,%1,%2,%3}, [%4];" \
                 : "=r"((r)[0]), "=r"((r)[1]), "=r"((r)[2]), "=r"((r)[3]) : "r"(a))

__device__ __forceinline__ void mma16816(float* d, const uint32_t* a,
                                         uint32_t b0, uint32_t b1) {
    asm volatile(
        "mma.sync.aligned.m16n8k16.row.col.f32.f16.f16.f32 "
        "{%0,%1,%2,%3}, {%4,%5,%6,%7}, {%8,%9}, {%0,%1,%2,%3};"
        : "+f"(d[0]), "+f"(d[1]), "+f"(d[2]), "+f"(d[3])
        : "r"(a[0]), "r"(a[1]), "r"(a[2]), "r"(a[3]), "r"(b0), "r"(b1));
}

// ---------------- GEMM (mma.sync fp16, 2-product split) --------------------
// BM=256, BN=128, BK=32, 512 threads (16 warps, 4m x 4n), warp tile 64x32.
// A in fp16 (hi only); B split into fp16 hi + fp16 lo (2 MMA products).
#define BM 256
#define BN 128
#define BK 32
#define ROWB 80                          // padded row: 32 fp16 = 64B -> 80B
#define A_BYTES (256 * ROWB)             // 20480
#define B_BYTES (128 * ROWB)             // 10240
#define STAGEB (A_BYTES + 2 * B_BYTES)   // 40960
#define NSTAGE 4
#define GEMM_SMEM (NSTAGE * STAGEB)      // 163840

__device__ __forceinline__ void load_chunk(
    uint32_t s0, int tid, int k0,
    const __half* __restrict__ Ah, int lda, int bm,
    const __half* __restrict__ Bh, const __half* __restrict__ Bl,
    int ldb, int bn)
{
#pragma unroll
    for (int r = 0; r < 2; r++) {        // A hi: 256 rows x 4 segs
        int e = tid + r * 512;
        int row = e >> 2, seg = e & 3;
        CP_ASYNC16(s0 + (uint32_t)row * ROWB + seg * 16,
                   Ah + (size_t)(bm + row) * lda + k0 + seg * 8);
    }
    {
        int row = tid >> 2, seg = tid & 3;   // B: 128 rows x 4 segs
        size_t gb = (size_t)(bn + row) * ldb + k0 + seg * 8;
        uint32_t off = (uint32_t)row * ROWB + seg * 16;
        CP_ASYNC16(s0 + A_BYTES + off,           Bh + gb);
        CP_ASYNC16(s0 + A_BYTES + B_BYTES + off, Bl + gb);
    }
}

// ACT: 0 none, 1 ELU.  OUT16: 1 -> write fp16 (hi), 0 -> write fp32.
template <int ACT, int OUT16>
__global__ __launch_bounds__(512, 1)
void tgemm_k(const __half* __restrict__ Ah, int lda, long sAn,
             const __half* __restrict__ Bh, const __half* __restrict__ Bl,
             int ldb, long sBn,
             const float* __restrict__ bias, int sBiasN,
             float* __restrict__ Cf, __half* __restrict__ Ch,
             int ldc, long sCn, int K)
{
    extern __shared__ char smem[];
    const uint32_t sbase = smem_u32(smem);
    const int tid = threadIdx.x;
    const int nb = blockIdx.z;
    Ah += (size_t)nb * sAn;
    Bh += (size_t)nb * sBn;  Bl += (size_t)nb * sBn;
    bias += (size_t)nb * sBiasN;
    const size_t coff = (size_t)nb * sCn;
    const int bm = blockIdx.y * BM, bn = blockIdx.x * BN;

    const int lane = tid & 31, wid = tid >> 5;
    const int wm = wid & 3, wn = wid >> 2;    // 4(m) x 4(n) warp grid
    const int lr = lane & 15, lc = lane >> 4;

    float acc[4][4][4];                        // [mt][n8-tile][frag]
#pragma unroll
    for (int a = 0; a < 4; a++)
#pragma unroll
        for (int b = 0; b < 4; b++)
#pragma unroll
            for (int c = 0; c < 4; c++) acc[a][b][c] = 0.f;

    const int nk = K / BK;
#pragma unroll
    for (int j = 0; j < 3; j++) {
        if (j < nk)
            load_chunk(sbase + j * STAGEB, tid, j * BK, Ah, lda, bm, Bh, Bl, ldb, bn);
        CP_COMMIT();
    }

    for (int i = 0; i < nk; i++) {
        CP_WAIT2();
        __syncthreads();
        const uint32_t sb = sbase + (uint32_t)(i & 3) * STAGEB;

#pragma unroll
        for (int ks = 0; ks < 2; ks++) {
            const uint32_t koff = (uint32_t)(ks * 16 + lc * 8) * 2;
            uint32_t ah[4][4];
#pragma unroll
            for (int mt = 0; mt < 4; mt++) {
                uint32_t ra = sb + (uint32_t)(wm * 64 + mt * 16 + lr) * ROWB + koff;
                LDSM4(ah[mt], ra);
            }
#pragma unroll
            for (int nt = 0; nt < 2; nt++) {
                uint32_t rb = sb + A_BYTES +
                              (uint32_t)(wn * 32 + nt * 16 + lr) * ROWB + koff;
                uint32_t bh[4], bl[4];
                LDSM4(bh, rb);
                LDSM4(bl, rb + B_BYTES);
#pragma unroll
                for (int mt = 0; mt < 4; mt++) {
                    mma16816(acc[mt][nt * 2 + 0], ah[mt], bh[0], bh[2]);
                    mma16816(acc[mt][nt * 2 + 1], ah[mt], bh[1], bh[3]);
                }
#pragma unroll
                for (int mt = 0; mt < 4; mt++) {
                    mma16816(acc[mt][nt * 2 + 0], ah[mt], bl[0], bl[2]);
                    mma16816(acc[mt][nt * 2 + 1], ah[mt], bl[1], bl[3]);
                }
            }
        }

        int j = i + 3;
        if (j < nk)
            load_chunk(sbase + (uint32_t)(j & 3) * STAGEB, tid, j * BK,
                       Ah, lda, bm, Bh, Bl, ldb, bn);
        CP_COMMIT();
    }

    // Epilogue: warp tile 64x32; thread owns 2 cols x (2 rows per n8-tile).
    const int rbase = bm + wm * 64 + (lane >> 2);
    const int cbase = bn + wn * 32 + (lane & 3) * 2;
#pragma unroll
    for (int mt = 0; mt < 4; mt++) {
#pragma unroll
        for (int t8 = 0; t8 < 4; t8++) {
            const int r = rbase + mt * 16;
            const int c = cbase + t8 * 8;
            const float b0 = bias[c], b1 = bias[c + 1];
            float v00 = acc[mt][t8][0] + b0, v01 = acc[mt][t8][1] + b1;
            float v10 = acc[mt][t8][2] + b0, v11 = acc[mt][t8][3] + b1;
            if (ACT == 1) {
                v00 = v00 > 0.f ? v00 : expm1f(v00);
                v01 = v01 > 0.f ? v01 : expm1f(v01);
                v10 = v10 > 0.f ? v10 : expm1f(v10);
                v11 = v11 > 0.f ? v11 : expm1f(v11);
            }
            if (OUT16) {
                __half2 H0 = __floats2half2_rn(v00, v01);
                __half2 H1 = __floats2half2_rn(v10, v11);
                *(uint32_t*)(Ch + coff + (size_t)r * ldc + c) =
                    *reinterpret_cast<uint32_t*>(&H0);
                *(uint32_t*)(Ch + coff + (size_t)(r + 8) * ldc + c) =
                    *reinterpret_cast<uint32_t*>(&H1);
            } else {
                *(float2*)(Cf + coff + (size_t)r * ldc + c) = make_float2(v00, v01);
                *(float2*)(Cf + coff + (size_t)(r + 8) * ldc + c) = make_float2(v10, v11);
            }
        }
    }
}

// ---------------- convert fp32 -> fp16 -------------------------------------
__global__ __launch_bounds__(256)
void cvt16_k(const float* __restrict__ src, __half* __restrict__ dst, size_t n)
{
    size_t i = ((size_t)blockIdx.x * blockDim.x + threadIdx.x) * 4;
    if (i >= n) return;
    float4 v = *(const float4*)(src + i);
    __half2 h0 = __floats2half2_rn(v.x, v.y);
    __half2 h1 = __floats2half2_rn(v.z, v.w);
    uint2 o = { *reinterpret_cast<uint32_t*>(&h0), *reinterpret_cast<uint32_t*>(&h1) };
    *(uint2*)((unsigned short*)dst + i) = o;
}

// ---------------- transpose + split: W[k][n] -> Wt_hi/lo[n][k] (fp16) ------
__global__ __launch_bounds__(256)
void tsplit_k(const float* __restrict__ src, __half* __restrict__ hi,
              __half* __restrict__ lo, int K, int Ncol)
{
    __shared__ float t[32][33];
    const size_t zoff = (size_t)blockIdx.z * K * Ncol;
    src += zoff; hi += zoff; lo += zoff;
    int k0 = blockIdx.y * 32, n0 = blockIdx.x * 32;
#pragma unroll
    for (int r = 0; r < 4; r++)
        t[threadIdx.y + r * 8][threadIdx.x] =
            src[(size_t)(k0 + threadIdx.y + r * 8) * Ncol + n0 + threadIdx.x];
    __syncthreads();
#pragma unroll
    for (int r = 0; r < 4; r++) {
        int n = n0 + threadIdx.y + r * 8;
        int k = k0 + threadIdx.x;
        float v = t[threadIdx.x][threadIdx.y + r * 8];
        __half h = __float2half_rn(v);
        float rr = v - __half2float(h);
        hi[(size_t)n * K + k] = h;
        lo[(size_t)n * K + k] = __float2half_rn(rr);
    }
}

// ---------------- GLU elementwise ------------------------------------------
__global__ void glu_k(float* __restrict__ a, const float* __restrict__ b, size_t n)
{
    size_t i = (size_t)blockIdx.x * blockDim.x + threadIdx.x;
    if (i < n) {
        float s = 1.f / (1.f + expf(-a[i]));
        a[i] = s * b[i];
    }
}

// ---------------- LN(4096) + softmax over variable axis --------------------
__global__ __launch_bounds__(256)
void ln_softmax_k(const float* __restrict__ x, const float* __restrict__ g,
                  const float* __restrict__ gamma, const float* __restrict__ beta,
                  float* __restrict__ w)
{
    __shared__ float s[FEAT];
    __shared__ float red[8];
    const int b = blockIdx.x, t = threadIdx.x;
    const int lane = t & 31, wid = t >> 5;
    const float* xb = x + (size_t)b * FEAT;
    const float* gb = g + (size_t)b * FEAT;

    float lsum = 0.f;
    for (int i = t; i < FEAT; i += 256) {
        float v = xb[i] + gb[i];
        s[i] = v; lsum += v;
    }
#pragma unroll
    for (int o = 16; o; o >>= 1) lsum += __shfl_xor_sync(0xffffffff, lsum, o);
    if (lane == 0) red[wid] = lsum;
    __syncthreads();
    float tot = 0.f;
#pragma unroll
    for (int i = 0; i < 8; i++) tot += red[i];
    float mean = tot * (1.f / FEAT);
    __syncthreads();

    float lvar = 0.f;
    for (int i = t; i < FEAT; i += 256) { float d = s[i] - mean; lvar += d * d; }
#pragma unroll
    for (int o = 16; o; o >>= 1) lvar += __shfl_xor_sync(0xffffffff, lvar, o);
    if (lane == 0) red[wid] = lvar;
    __syncthreads();
    float vtot = 0.f;
#pragma unroll
    for (int i = 0; i < 8; i++) vtot += red[i];
    float rstd = rsqrtf(vtot * (1.f / FEAT) + 1e-5f);

    for (int i = t; i < FEAT; i += 256)
        s[i] = (s[i] - mean) * rstd * gamma[i] + beta[i];
    __syncthreads();

    float c[NVAR];
    float m = -1e30f;
#pragma unroll
    for (int n = 0; n < NVAR; n++) { c[n] = s[n * DDIM + t]; m = fmaxf(m, c[n]); }
    float sum = 0.f;
#pragma unroll
    for (int n = 0; n < NVAR; n++) { c[n] = expf(c[n] - m); sum += c[n]; }
    float inv = 1.f / sum;
    float* wb = w + (size_t)b * FEAT;
#pragma unroll
    for (int n = 0; n < NVAR; n++) wb[n * DDIM + t] = c[n] * inv;
}

// ---------------- per-(b,n) LN(256) + weighted combine ---------------------
__global__ __launch_bounds__(256)
void combine_k(const float* __restrict__ x, const float* __restrict__ gv,
               const float* __restrict__ w, const float* __restrict__ vlng,
               const float* __restrict__ vlnb, float* __restrict__ out)
{
    __shared__ float red[8];
    const int b = blockIdx.x, t = threadIdx.x;
    const int lane = t & 31, wid = t >> 5;

    float acc = 0.f;
    for (int n = 0; n < NVAR; n++) {
        size_t idx = (size_t)b * FEAT + n * DDIM + t;
        float v = x[idx] + gv[idx];
        float s1 = v;
#pragma unroll
        for (int o = 16; o; o >>= 1) s1 += __shfl_xor_sync(0xffffffff, s1, o);
        __syncthreads();
        if (lane == 0) red[wid] = s1;
        __syncthreads();
        float tot = 0.f;
#pragma unroll
        for (int i = 0; i < 8; i++) tot += red[i];
        float mean = tot * (1.f / DDIM);

        float d = v - mean;
        float s2 = d * d;
#pragma unroll
        for (int o = 16; o; o >>= 1) s2 += __shfl_xor_sync(0xffffffff, s2, o);
        __syncthreads();
        if (lane == 0) red[wid] = s2;
        __syncthreads();
        float vtot = 0.f;
#pragma unroll
        for (int i = 0; i < 8; i++) vtot += red[i];
        float rstd = rsqrtf(vtot * (1.f / DDIM) + 1e-5f);

        float yv = d * rstd * vlng[n * DDIM + t] + vlnb[n * DDIM + t];
        acc += w[idx] * yv;
    }
    out[(size_t)b * DDIM + t] = acc;
}

// ---------------- launch ----------------------------------------------------
extern "C" void kernel_launch(void* const* d_in, const int* in_sizes, int n_in,
                              void* d_out, int out_size)
{
    const float* x    = (const float*)d_in[0];
    const float* vW2  = (const float*)d_in[1];
    const float* vb2  = (const float*)d_in[2];
    const float* vW1  = (const float*)d_in[3];
    const float* vb1  = (const float*)d_in[4];
    const float* vW4  = (const float*)d_in[5];
    const float* vb4  = (const float*)d_in[6];
    const float* vW5  = (const float*)d_in[7];
    const float* vb5  = (const float*)d_in[8];
    const float* vlng = (const float*)d_in[9];
    const float* vlnb = (const float*)d_in[10];
    const float* cW2  = (const float*)d_in[11];
    const float* cb2  = (const float*)d_in[12];
    const float* cW1  = (const float*)d_in[13];
    const float* cb1  = (const float*)d_in[14];
    const float* cW4  = (const float*)d_in[15];
    const float* cb4  = (const float*)d_in[16];
    const float* cW5  = (const float*)d_in[17];
    const float* cb5  = (const float*)d_in[18];
    const float* clng = (const float*)d_in[19];
    const float* clnb = (const float*)d_in[20];
    float* out = (float*)d_out;

    float *buf0, *buf1, *buf2, *buf3;
    cudaGetSymbolAddress((void**)&buf0, g_buf0);
    cudaGetSymbolAddress((void**)&buf1, g_buf1);
    cudaGetSymbolAddress((void**)&buf2, g_buf2);
    cudaGetSymbolAddress((void**)&buf3, g_buf3);
    __half *xh, *hh, *eh;
    cudaGetSymbolAddress((void**)&xh, g_xh);
    cudaGetSymbolAddress((void**)&hh, g_hh);
    cudaGetSymbolAddress((void**)&eh, g_eh);
    __half *cW2h, *cW2l, *cW1h, *cW1l, *cW4h, *cW4l, *cW5h, *cW5l;
    cudaGetSymbolAddress((void**)&cW2h, g_cW2h); cudaGetSymbolAddress((void**)&cW2l, g_cW2l);
    cudaGetSymbolAddress((void**)&cW1h, g_cW1h); cudaGetSymbolAddress((void**)&cW1l, g_cW1l);
    cudaGetSymbolAddress((void**)&cW4h, g_cW4h); cudaGetSymbolAddress((void**)&cW4l, g_cW4l);
    cudaGetSymbolAddress((void**)&cW5h, g_cW5h); cudaGetSymbolAddress((void**)&cW5l, g_cW5l);
    __half *vW2h, *vW2l, *vW1h, *vW1l, *vW4h, *vW4l, *vW5h, *vW5l;
    cudaGetSymbolAddress((void**)&vW2h, g_vW2h); cudaGetSymbolAddress((void**)&vW2l, g_vW2l);
    cudaGetSymbolAddress((void**)&vW1h, g_vW1h); cudaGetSymbolAddress((void**)&vW1l, g_vW1l);
    cudaGetSymbolAddress((void**)&vW4h, g_vW4h); cudaGetSymbolAddress((void**)&vW4l, g_vW4l);
    cudaGetSymbolAddress((void**)&vW5h, g_vW5h); cudaGetSymbolAddress((void**)&vW5l, g_vW5l);

    cudaFuncSetAttribute(tgemm_k<1, 1>, cudaFuncAttributeMaxDynamicSharedMemorySize, GEMM_SMEM);
    cudaFuncSetAttribute(tgemm_k<0, 1>, cudaFuncAttributeMaxDynamicSharedMemorySize, GEMM_SMEM);
    cudaFuncSetAttribute(tgemm_k<0, 0>, cudaFuncAttributeMaxDynamicSharedMemorySize, GEMM_SMEM);

    const size_t NE = NELEM;

    // ---- conversions ----
    cvt16_k<<<(unsigned)(NE / 1024), 256>>>(x, xh, NE);
    {
        dim3 g(128, 128, 1), b(32, 8);
        tsplit_k<<<g, b>>>(cW2, cW2h, cW2l, FEAT, FEAT);
        tsplit_k<<<g, b>>>(cW1, cW1h, cW1l, FEAT, FEAT);
        tsplit_k<<<g, b>>>(cW4, cW4h, cW4l, FEAT, FEAT);
        tsplit_k<<<g, b>>>(cW5, cW5h, cW5l, FEAT, FEAT);
        dim3 gv(8, 8, NVAR);
        tsplit_k<<<gv, b>>>(vW2, vW2h, vW2l, DDIM, DDIM);
        tsplit_k<<<gv, b>>>(vW1, vW1h, vW1l, DDIM, DDIM);
        tsplit_k<<<gv, b>>>(vW4, vW4h, vW4l, DDIM, DDIM);
        tsplit_k<<<gv, b>>>(vW5, vW5h, vW5l, DDIM, DDIM);
    }

    dim3 gridC(FEAT / BN, BATCH / BM, 1);     // 32 x 16
    dim3 gridV(DDIM / BN, BATCH / BM, NVAR);  // 2 x 16 x 16
    dim3 blk(512);

    // ---- concat GRN ----
    tgemm_k<1, 1><<<gridC, blk, GEMM_SMEM>>>(xh, FEAT, 0, cW2h, cW2l, FEAT, 0,
                                             cb2, 0, nullptr, hh, FEAT, 0, FEAT);
    tgemm_k<0, 1><<<gridC, blk, GEMM_SMEM>>>(hh, FEAT, 0, cW1h, cW1l, FEAT, 0,
                                             cb1, 0, nullptr, eh, FEAT, 0, FEAT);
    tgemm_k<0, 0><<<gridC, blk, GEMM_SMEM>>>(eh, FEAT, 0, cW4h, cW4l, FEAT, 0,
                                             cb4, 0, buf0, nullptr, FEAT, 0, FEAT);
    tgemm_k<0, 0><<<gridC, blk, GEMM_SMEM>>>(eh, FEAT, 0, cW5h, cW5l, FEAT, 0,
                                             cb5, 0, buf1, nullptr, FEAT, 0, FEAT);
    glu_k<<<(unsigned)(NE / 256), 256>>>(buf0, buf1, NE);
    ln_softmax_k<<<BATCH, 256>>>(x, buf0, clng, clnb, buf1);   // weights -> buf1

    // ---- per-variable GRNs ----
    tgemm_k<1, 1><<<gridV, blk, GEMM_SMEM>>>(xh, FEAT, DDIM, vW2h, vW2l, DDIM,
                                             (long)DDIM * DDIM, vb2, DDIM,
                                             nullptr, hh, FEAT, DDIM, DDIM);
    tgemm_k<0, 1><<<gridV, blk, GEMM_SMEM>>>(hh, FEAT, DDIM, vW1h, vW1l, DDIM,
                                             (long)DDIM * DDIM, vb1, DDIM,
                                             nullptr, eh, FEAT, DDIM, DDIM);
    tgemm_k<0, 0><<<gridV, blk, GEMM_SMEM>>>(eh, FEAT, DDIM, vW4h, vW4l, DDIM,
                                             (long)DDIM * DDIM, vb4, DDIM,
                                             buf2, nullptr, FEAT, DDIM, DDIM);
    tgemm_k<0, 0><<<gridV, blk, GEMM_SMEM>>>(eh, FEAT, DDIM, vW5h, vW5l, DDIM,
                                             (long)DDIM * DDIM, vb5, DDIM,
                                             buf3, nullptr, FEAT, DDIM, DDIM);
    glu_k<<<(unsigned)(NE / 256), 256>>>(buf2, buf3, NE);

    combine_k<<<BATCH, 256>>>(x, buf2, buf1, vlng, vlnb, out);
}

// round 7
// speedup vs baseline: 4.4274x; 1.4156x over previous
#include <cuda_runtime.h>
#include <cuda_fp16.h>
#include <math.h>
#include <stdint.h>

#define BATCH 4096
#define NVAR  16
#define DDIM  256
#define FEAT  4096
#define NELEM ((size_t)BATCH * FEAT)     // 16,777,216
#define VWN   ((size_t)NVAR * DDIM * DDIM)

// ---------------- scratch (device globals; allocation forbidden) -----------
__device__ __align__(256) float g_buf0[NELEM];
__device__ __align__(256) float g_buf1[NELEM];
__device__ __align__(256) float g_buf2[NELEM];
// fp16 activations
__device__ __align__(256) __half g_xh[NELEM];
__device__ __align__(256) __half g_hh[NELEM];
__device__ __align__(256) __half g_eh[NELEM];
// transposed fp16 weights
__device__ __align__(256) __half g_cW2h[NELEM];
__device__ __align__(256) __half g_cW1h[NELEM];
__device__ __align__(256) __half g_cW4h[NELEM];
__device__ __align__(256) __half g_cW5h[NELEM];
__device__ __align__(256) __half g_vW2h[VWN];
__device__ __align__(256) __half g_vW1h[VWN];
__device__ __align__(256) __half g_vW4h[VWN];
__device__ __align__(256) __half g_vW5h[VWN];

// ---------------- helpers ---------------------------------------------------
__device__ __forceinline__ uint32_t smem_u32(const void* p) {
    uint32_t a;
    asm("{ .reg .u64 t; cvta.to.shared.u64 t, %1; cvt.u32.u64 %0, t; }"
        : "=r"(a) : "l"(p));
    return a;
}

#define CP_ASYNC16(dst, src) \
    asm volatile("cp.async.cg.shared.global [%0], [%1], 16;" :: "r"(dst), "l"(src))
#define CP_COMMIT() asm volatile("cp.async.commit_group;" ::: "memory")
#define CP_WAIT3()  asm volatile("cp.async.wait_group 3;" ::: "memory")

#define LDSM4(r, a) \
    asm volatile("ldmatrix.sync.aligned.m8n8.x4.shared.b16 {%0,%1,%2,%3}, [%4];" \
                 : "=r"((r)[0]), "=r"((r)[1]), "=r"((r)[2]), "=r"((r)[3]) : "r"(a))

__device__ __forceinline__ void mma16816(float* d, const uint32_t* a,
                                         uint32_t b0, uint32_t b1) {
    asm volatile(
        "mma.sync.aligned.m16n8k16.row.col.f32.f16.f16.f32 "
        "{%0,%1,%2,%3}, {%4,%5,%6,%7}, {%8,%9}, {%0,%1,%2,%3};"
        : "+f"(d[0]), "+f"(d[1]), "+f"(d[2]), "+f"(d[3])
        : "r"(a[0]), "r"(a[1]), "r"(a[2]), "r"(a[3]), "r"(b0), "r"(b1));
}

// ---------------- GEMM (mma.sync fp16, single product) ---------------------
// BM=256, BN=128, BK=32, 512 threads (16 warps, 4m x 4n), warp tile 64x32.
#define BM 256
#define BN 128
#define BK 32
#define ROWB 80                          // padded row: 32 fp16 = 64B -> 80B
#define A_BYTES (256 * ROWB)             // 20480
#define B_BYTES (128 * ROWB)             // 10240
#define STAGEB (A_BYTES + B_BYTES)       // 30720
#define NSTAGE 5
#define GEMM_SMEM (NSTAGE * STAGEB)      // 153600

__device__ __forceinline__ void load_chunk(
    uint32_t s0, int tid, int k0,
    const __half* __restrict__ Ah, int lda, int bm,
    const __half* __restrict__ Bh, int ldb, int bn)
{
#pragma unroll
    for (int r = 0; r < 2; r++) {        // A: 256 rows x 4 segs
        int e = tid + r * 512;
        int row = e >> 2, seg = e & 3;
        CP_ASYNC16(s0 + (uint32_t)row * ROWB + seg * 16,
                   Ah + (size_t)(bm + row) * lda + k0 + seg * 8);
    }
    {
        int row = tid >> 2, seg = tid & 3;   // B: 128 rows x 4 segs
        CP_ASYNC16(s0 + A_BYTES + (uint32_t)row * ROWB + seg * 16,
                   Bh + (size_t)(bn + row) * ldb + k0 + seg * 8);
    }
}

// ACT: 0 none, 1 ELU, 2 GLU (v = sigmoid(aux)*v).
// OUT16: 1 -> write fp16, 0 -> write fp32.
template <int ACT, int OUT16>
__global__ __launch_bounds__(512, 1)
void tgemm_k(const __half* __restrict__ Ah, int lda, long sAn,
             const __half* __restrict__ Bh, int ldb, long sBn,
             const float* __restrict__ bias, int sBiasN,
             const float* __restrict__ Aux,
             float* __restrict__ Cf, __half* __restrict__ Ch,
             int ldc, long sCn, int K)
{
    extern __shared__ char smem[];
    const uint32_t sbase = smem_u32(smem);
    const int tid = threadIdx.x;
    const int nb = blockIdx.z;
    Ah += (size_t)nb * sAn;
    Bh += (size_t)nb * sBn;
    bias += (size_t)nb * sBiasN;
    const size_t coff = (size_t)nb * sCn;
    const int bm = blockIdx.y * BM, bn = blockIdx.x * BN;

    const int lane = tid & 31, wid = tid >> 5;
    const int wm = wid & 3, wn = wid >> 2;    // 4(m) x 4(n) warp grid
    const int lr = lane & 15, lc = lane >> 4;

    float acc[4][4][4];                        // [mt][n8-tile][frag]
#pragma unroll
    for (int a = 0; a < 4; a++)
#pragma unroll
        for (int b = 0; b < 4; b++)
#pragma unroll
            for (int c = 0; c < 4; c++) acc[a][b][c] = 0.f;

    const int nk = K / BK;
#pragma unroll
    for (int j = 0; j < 4; j++) {
        if (j < nk)
            load_chunk(sbase + j * STAGEB, tid, j * BK, Ah, lda, bm, Bh, ldb, bn);
        CP_COMMIT();
    }

    int stR = 0, stW = 4;
    for (int i = 0; i < nk; i++) {
        CP_WAIT3();
        __syncthreads();
        const uint32_t sb = sbase + (uint32_t)stR * STAGEB;

#pragma unroll
        for (int ks = 0; ks < 2; ks++) {
            const uint32_t koff = (uint32_t)(ks * 16 + lc * 8) * 2;
            uint32_t ah[4][4];
#pragma unroll
            for (int mt = 0; mt < 4; mt++) {
                uint32_t ra = sb + (uint32_t)(wm * 64 + mt * 16 + lr) * ROWB + koff;
                LDSM4(ah[mt], ra);
            }
#pragma unroll
            for (int nt = 0; nt < 2; nt++) {
                uint32_t rb = sb + A_BYTES +
                              (uint32_t)(wn * 32 + nt * 16 + lr) * ROWB + koff;
                uint32_t bh[4];
                LDSM4(bh, rb);
#pragma unroll
                for (int mt = 0; mt < 4; mt++) {
                    mma16816(acc[mt][nt * 2 + 0], ah[mt], bh[0], bh[2]);
                    mma16816(acc[mt][nt * 2 + 1], ah[mt], bh[1], bh[3]);
                }
            }
        }

        int j = i + 4;
        if (j < nk)
            load_chunk(sbase + (uint32_t)stW * STAGEB, tid, j * BK,
                       Ah, lda, bm, Bh, ldb, bn);
        CP_COMMIT();
        stR = (stR + 1 == NSTAGE) ? 0 : stR + 1;
        stW = (stW + 1 == NSTAGE) ? 0 : stW + 1;
    }

    // Epilogue: warp tile 64x32; thread owns 2 cols x (2 rows per n8-tile).
    const int rbase = bm + wm * 64 + (lane >> 2);
    const int cbase = bn + wn * 32 + (lane & 3) * 2;
#pragma unroll
    for (int mt = 0; mt < 4; mt++) {
#pragma unroll
        for (int t8 = 0; t8 < 4; t8++) {
            const int r = rbase + mt * 16;
            const int c = cbase + t8 * 8;
            const float b0 = bias[c], b1 = bias[c + 1];
            float v00 = acc[mt][t8][0] + b0, v01 = acc[mt][t8][1] + b1;
            float v10 = acc[mt][t8][2] + b0, v11 = acc[mt][t8][3] + b1;
            if (ACT == 1) {
                v00 = v00 > 0.f ? v00 : expm1f(v00);
                v01 = v01 > 0.f ? v01 : expm1f(v01);
                v10 = v10 > 0.f ? v10 : expm1f(v10);
                v11 = v11 > 0.f ? v11 : expm1f(v11);
            }
            if (ACT == 2) {
                float2 a0 = *(const float2*)(Aux + coff + (size_t)r * ldc + c);
                float2 a1 = *(const float2*)(Aux + coff + (size_t)(r + 8) * ldc + c);
                v00 *= 1.f / (1.f + expf(-a0.x));
                v01 *= 1.f / (1.f + expf(-a0.y));
                v10 *= 1.f / (1.f + expf(-a1.x));
                v11 *= 1.f / (1.f + expf(-a1.y));
            }
            if (OUT16) {
                __half2 H0 = __floats2half2_rn(v00, v01);
                __half2 H1 = __floats2half2_rn(v10, v11);
                *(uint32_t*)(Ch + coff + (size_t)r * ldc + c) =
                    *reinterpret_cast<uint32_t*>(&H0);
                *(uint32_t*)(Ch + coff + (size_t)(r + 8) * ldc + c) =
                    *reinterpret_cast<uint32_t*>(&H1);
            } else {
                *(float2*)(Cf + coff + (size_t)r * ldc + c) = make_float2(v00, v01);
                *(float2*)(Cf + coff + (size_t)(r + 8) * ldc + c) = make_float2(v10, v11);
            }
        }
    }
}

// ---------------- convert fp32 -> fp16 -------------------------------------
__global__ __launch_bounds__(256)
void cvt16_k(const float* __restrict__ src, __half* __restrict__ dst, size_t n)
{
    size_t i = ((size_t)blockIdx.x * blockDim.x + threadIdx.x) * 4;
    if (i >= n) return;
    float4 v = *(const float4*)(src + i);
    __half2 h0 = __floats2half2_rn(v.x, v.y);
    __half2 h1 = __floats2half2_rn(v.z, v.w);
    uint2 o = { *reinterpret_cast<uint32_t*>(&h0), *reinterpret_cast<uint32_t*>(&h1) };
    *(uint2*)((unsigned short*)dst + i) = o;
}

// ---------------- transpose + convert: W[k][n] -> Wt[n][k] (fp16) ----------
__global__ __launch_bounds__(256)
void tcvt_k(const float* __restrict__ src, __half* __restrict__ hi, int K, int Ncol)
{
    __shared__ float t[32][33];
    const size_t zoff = (size_t)blockIdx.z * K * Ncol;
    src += zoff; hi += zoff;
    int k0 = blockIdx.y * 32, n0 = blockIdx.x * 32;
#pragma unroll
    for (int r = 0; r < 4; r++)
        t[threadIdx.y + r * 8][threadIdx.x] =
            src[(size_t)(k0 + threadIdx.y + r * 8) * Ncol + n0 + threadIdx.x];
    __syncthreads();
#pragma unroll
    for (int r = 0; r < 4; r++) {
        int n = n0 + threadIdx.y + r * 8;
        int k = k0 + threadIdx.x;
        hi[(size_t)n * K + k] = __float2half_rn(t[threadIdx.x][threadIdx.y + r * 8]);
    }
}

// ---------------- LN(4096) + softmax over variable axis --------------------
__global__ __launch_bounds__(256)
void ln_softmax_k(const float* __restrict__ x, const float* __restrict__ g,
                  const float* __restrict__ gamma, const float* __restrict__ beta,
                  float* __restrict__ w)
{
    __shared__ float s[FEAT];
    __shared__ float red[8];
    const int b = blockIdx.x, t = threadIdx.x;
    const int lane = t & 31, wid = t >> 5;
    const float* xb = x + (size_t)b * FEAT;
    const float* gb = g + (size_t)b * FEAT;

    float lsum = 0.f;
    for (int i = t; i < FEAT; i += 256) {
        float v = xb[i] + gb[i];
        s[i] = v; lsum += v;
    }
#pragma unroll
    for (int o = 16; o; o >>= 1) lsum += __shfl_xor_sync(0xffffffff, lsum, o);
    if (lane == 0) red[wid] = lsum;
    __syncthreads();
    float tot = 0.f;
#pragma unroll
    for (int i = 0; i < 8; i++) tot += red[i];
    float mean = tot * (1.f / FEAT);
    __syncthreads();

    float lvar = 0.f;
    for (int i = t; i < FEAT; i += 256) { float d = s[i] - mean; lvar += d * d; }
#pragma unroll
    for (int o = 16; o; o >>= 1) lvar += __shfl_xor_sync(0xffffffff, lvar, o);
    if (lane == 0) red[wid] = lvar;
    __syncthreads();
    float vtot = 0.f;
#pragma unroll
    for (int i = 0; i < 8; i++) vtot += red[i];
    float rstd = rsqrtf(vtot * (1.f / FEAT) + 1e-5f);

    for (int i = t; i < FEAT; i += 256)
        s[i] = (s[i] - mean) * rstd * gamma[i] + beta[i];
    __syncthreads();

    float c[NVAR];
    float m = -1e30f;
#pragma unroll
    for (int n = 0; n < NVAR; n++) { c[n] = s[n * DDIM + t]; m = fmaxf(m, c[n]); }
    float sum = 0.f;
#pragma unroll
    for (int n = 0; n < NVAR; n++) { c[n] = expf(c[n] - m); sum += c[n]; }
    float inv = 1.f / sum;
    float* wb = w + (size_t)b * FEAT;
#pragma unroll
    for (int n = 0; n < NVAR; n++) wb[n * DDIM + t] = c[n] * inv;
}

// ---------------- per-(b,n) LN(256) + weighted combine ---------------------
__global__ __launch_bounds__(256)
void combine_k(const float* __restrict__ x, const float* __restrict__ gv,
               const float* __restrict__ w, const float* __restrict__ vlng,
               const float* __restrict__ vlnb, float* __restrict__ out)
{
    __shared__ float red[8];
    const int b = blockIdx.x, t = threadIdx.x;
    const int lane = t & 31, wid = t >> 5;

    float acc = 0.f;
    for (int n = 0; n < NVAR; n++) {
        size_t idx = (size_t)b * FEAT + n * DDIM + t;
        float v = x[idx] + gv[idx];
        float s1 = v;
#pragma unroll
        for (int o = 16; o; o >>= 1) s1 += __shfl_xor_sync(0xffffffff, s1, o);
        __syncthreads();
        if (lane == 0) red[wid] = s1;
        __syncthreads();
        float tot = 0.f;
#pragma unroll
        for (int i = 0; i < 8; i++) tot += red[i];
        float mean = tot * (1.f / DDIM);

        float d = v - mean;
        float s2 = d * d;
#pragma unroll
        for (int o = 16; o; o >>= 1) s2 += __shfl_xor_sync(0xffffffff, s2, o);
        __syncthreads();
        if (lane == 0) red[wid] = s2;
        __syncthreads();
        float vtot = 0.f;
#pragma unroll
        for (int i = 0; i < 8; i++) vtot += red[i];
        float rstd = rsqrtf(vtot * (1.f / DDIM) + 1e-5f);

        float yv = d * rstd * vlng[n * DDIM + t] + vlnb[n * DDIM + t];
        acc += w[idx] * yv;
    }
    out[(size_t)b * DDIM + t] = acc;
}

// ---------------- launch ----------------------------------------------------
extern "C" void kernel_launch(void* const* d_in, const int* in_sizes, int n_in,
                              void* d_out, int out_size)
{
    const float* x    = (const float*)d_in[0];
    const float* vW2  = (const float*)d_in[1];
    const float* vb2  = (const float*)d_in[2];
    const float* vW1  = (const float*)d_in[3];
    const float* vb1  = (const float*)d_in[4];
    const float* vW4  = (const float*)d_in[5];
    const float* vb4  = (const float*)d_in[6];
    const float* vW5  = (const float*)d_in[7];
    const float* vb5  = (const float*)d_in[8];
    const float* vlng = (const float*)d_in[9];
    const float* vlnb = (const float*)d_in[10];
    const float* cW2  = (const float*)d_in[11];
    const float* cb2  = (const float*)d_in[12];
    const float* cW1  = (const float*)d_in[13];
    const float* cb1  = (const float*)d_in[14];
    const float* cW4  = (const float*)d_in[15];
    const float* cb4  = (const float*)d_in[16];
    const float* cW5  = (const float*)d_in[17];
    const float* cb5  = (const float*)d_in[18];
    const float* clng = (const float*)d_in[19];
    const float* clnb = (const float*)d_in[20];
    float* out = (float*)d_out;

    float *buf0, *buf1, *buf2;
    cudaGetSymbolAddress((void**)&buf0, g_buf0);
    cudaGetSymbolAddress((void**)&buf1, g_buf1);
    cudaGetSymbolAddress((void**)&buf2, g_buf2);
    __half *xh, *hh, *eh;
    cudaGetSymbolAddress((void**)&xh, g_xh);
    cudaGetSymbolAddress((void**)&hh, g_hh);
    cudaGetSymbolAddress((void**)&eh, g_eh);
    __half *cW2h, *cW1h, *cW4h, *cW5h;
    cudaGetSymbolAddress((void**)&cW2h, g_cW2h);
    cudaGetSymbolAddress((void**)&cW1h, g_cW1h);
    cudaGetSymbolAddress((void**)&cW4h, g_cW4h);
    cudaGetSymbolAddress((void**)&cW5h, g_cW5h);
    __half *vW2h, *vW1h, *vW4h, *vW5h;
    cudaGetSymbolAddress((void**)&vW2h, g_vW2h);
    cudaGetSymbolAddress((void**)&vW1h, g_vW1h);
    cudaGetSymbolAddress((void**)&vW4h, g_vW4h);
    cudaGetSymbolAddress((void**)&vW5h, g_vW5h);

    cudaFuncSetAttribute(tgemm_k<1, 1>, cudaFuncAttributeMaxDynamicSharedMemorySize, GEMM_SMEM);
    cudaFuncSetAttribute(tgemm_k<0, 1>, cudaFuncAttributeMaxDynamicSharedMemorySize, GEMM_SMEM);
    cudaFuncSetAttribute(tgemm_k<0, 0>, cudaFuncAttributeMaxDynamicSharedMemorySize, GEMM_SMEM);
    cudaFuncSetAttribute(tgemm_k<2, 0>, cudaFuncAttributeMaxDynamicSharedMemorySize, GEMM_SMEM);

    const size_t NE = NELEM;

    // ---- conversions ----
    cvt16_k<<<(unsigned)(NE / 1024), 256>>>(x, xh, NE);
    {
        dim3 g(128, 128, 1), b(32, 8);
        tcvt_k<<<g, b>>>(cW2, cW2h, FEAT, FEAT);
        tcvt_k<<<g, b>>>(cW1, cW1h, FEAT, FEAT);
        tcvt_k<<<g, b>>>(cW4, cW4h, FEAT, FEAT);
        tcvt_k<<<g, b>>>(cW5, cW5h, FEAT, FEAT);
        dim3 gv(8, 8, NVAR);
        tcvt_k<<<gv, b>>>(vW2, vW2h, DDIM, DDIM);
        tcvt_k<<<gv, b>>>(vW1, vW1h, DDIM, DDIM);
        tcvt_k<<<gv, b>>>(vW4, vW4h, DDIM, DDIM);
        tcvt_k<<<gv, b>>>(vW5, vW5h, DDIM, DDIM);
    }

    dim3 gridC(FEAT / BN, BATCH / BM, 1);     // 32 x 16
    dim3 gridV(DDIM / BN, BATCH / BM, NVAR);  // 2 x 16 x 16
    dim3 blk(512);

    // ---- concat GRN ----
    tgemm_k<1, 1><<<gridC, blk, GEMM_SMEM>>>(xh, FEAT, 0, cW2h, FEAT, 0,
                                             cb2, 0, nullptr, nullptr, hh, FEAT, 0, FEAT);
    tgemm_k<0, 1><<<gridC, blk, GEMM_SMEM>>>(hh, FEAT, 0, cW1h, FEAT, 0,
                                             cb1, 0, nullptr, nullptr, eh, FEAT, 0, FEAT);
    tgemm_k<0, 0><<<gridC, blk, GEMM_SMEM>>>(eh, FEAT, 0, cW4h, FEAT, 0,
                                             cb4, 0, nullptr, buf0, nullptr, FEAT, 0, FEAT);
    // t5 with fused GLU: buf0 := sigmoid(buf0) * (eh @ cW5 + cb5)
    tgemm_k<2, 0><<<gridC, blk, GEMM_SMEM>>>(eh, FEAT, 0, cW5h, FEAT, 0,
                                             cb5, 0, buf0, buf0, nullptr, FEAT, 0, FEAT);
    ln_softmax_k<<<BATCH, 256>>>(x, buf0, clng, clnb, buf1);   // weights -> buf1

    // ---- per-variable GRNs ----
    tgemm_k<1, 1><<<gridV, blk, GEMM_SMEM>>>(xh, FEAT, DDIM, vW2h, DDIM,
                                             (long)DDIM * DDIM, vb2, DDIM,
                                             nullptr, nullptr, hh, FEAT, DDIM, DDIM);
    tgemm_k<0, 1><<<gridV, blk, GEMM_SMEM>>>(hh, FEAT, DDIM, vW1h, DDIM,
                                             (long)DDIM * DDIM, vb1, DDIM,
                                             nullptr, nullptr, eh, FEAT, DDIM, DDIM);
    tgemm_k<0, 0><<<gridV, blk, GEMM_SMEM>>>(eh, FEAT, DDIM, vW4h, DDIM,
                                             (long)DDIM * DDIM, vb4, DDIM,
                                             nullptr, buf2, nullptr, FEAT, DDIM, DDIM);
    tgemm_k<2, 0><<<gridV, blk, GEMM_SMEM>>>(eh, FEAT, DDIM, vW5h, DDIM,
                                             (long)DDIM * DDIM, vb5, DDIM,
                                             buf2, buf2, nullptr, FEAT, DDIM, DDIM);

    combine_k<<<BATCH, 256>>>(x, buf2, buf1, vlng, vlnb, out);
}

// round 8
// speedup vs baseline: 5.8851x; 1.3293x over previous
#include <cuda_runtime.h>
#include <cuda_fp16.h>
#include <math.h>
#include <stdint.h>

#define BATCH 4096
#define NVAR  16
#define DDIM  256
#define FEAT  4096
#define NELEM ((size_t)BATCH * FEAT)     // 16,777,216
#define VWN   ((size_t)NVAR * DDIM * DDIM)

// ---------------- scratch (device globals; allocation forbidden) -----------
__device__ __align__(256) float g_buf0[NELEM];   // concat GLU result
__device__ __align__(256) float g_buf1[NELEM];   // softmax weights
__device__ __align__(256) float g_buf2[NELEM];   // var GLU result
// fp16 activations
__device__ __align__(256) __half g_xh[NELEM];
__device__ __align__(256) __half g_hh[NELEM];    // concat h
__device__ __align__(256) __half g_eh[NELEM];    // concat e1
__device__ __align__(256) __half g_hv[NELEM];    // var h
__device__ __align__(256) __half g_ev[NELEM];    // var e1
// transposed fp16 weights
__device__ __align__(256) __half g_cW2h[NELEM];
__device__ __align__(256) __half g_cW1h[NELEM];
__device__ __align__(256) __half g_cW4h[NELEM];
__device__ __align__(256) __half g_cW5h[NELEM];
__device__ __align__(256) __half g_vW2h[VWN];
__device__ __align__(256) __half g_vW1h[VWN];
__device__ __align__(256) __half g_vW4h[VWN];
__device__ __align__(256) __half g_vW5h[VWN];

// ---------------- helpers ---------------------------------------------------
__device__ __forceinline__ uint32_t smem_u32(const void* p) {
    uint32_t a;
    asm("{ .reg .u64 t; cvta.to.shared.u64 t, %1; cvt.u32.u64 %0, t; }"
        : "=r"(a) : "l"(p));
    return a;
}

#define CP_ASYNC16(dst, src) \
    asm volatile("cp.async.cg.shared.global [%0], [%1], 16;" :: "r"(dst), "l"(src))
#define CP_COMMIT() asm volatile("cp.async.commit_group;" ::: "memory")
#define CP_WAIT3()  asm volatile("cp.async.wait_group 3;" ::: "memory")

#define LDSM4(r, a) \
    asm volatile("ldmatrix.sync.aligned.m8n8.x4.shared.b16 {%0,%1,%2,%3}, [%4];" \
                 : "=r"((r)[0]), "=r"((r)[1]), "=r"((r)[2]), "=r"((r)[3]) : "r"(a))

__device__ __forceinline__ void mma16816(float* d, const uint32_t* a,
                                         uint32_t b0, uint32_t b1) {
    asm volatile(
        "mma.sync.aligned.m16n8k16.row.col.f32.f16.f16.f32 "
        "{%0,%1,%2,%3}, {%4,%5,%6,%7}, {%8,%9}, {%0,%1,%2,%3};"
        : "+f"(d[0]), "+f"(d[1]), "+f"(d[2]), "+f"(d[3])
        : "r"(a[0]), "r"(a[1]), "r"(a[2]), "r"(a[3]), "r"(b0), "r"(b1));
}

// ---------------- merged GEMM (mma.sync fp16) ------------------------------
// BM=256, BN=128, BK=32, 512 threads (16 warps, 4m x 4n), warp tile 64x32.
#define BM 256
#define BN 128
#define BK 32
#define ROWB 80
#define A_BYTES (256 * ROWB)             // 20480
#define B_BYTES (128 * ROWB)             // 10240
#define STAGEB (A_BYTES + B_BYTES)       // 30720
#define NSTAGE 5
#define GEMM_SMEM (NSTAGE * STAGEB)      // 153600

struct GDesc {
    const __half* A;
    const __half* B;
    const float*  bias;
    const float*  Aux;
    float*        Cf;
    __half*       Ch;
    int  K, lda, ldb, ldc;
    long sAn, sBn, sBiasN, sCn;
    int  ntN, tilesPerZ;
};

__device__ __forceinline__ void load_chunk(
    uint32_t s0, int tid, int k0,
    const __half* __restrict__ Ah, int lda, int bm,
    const __half* __restrict__ Bh, int ldb, int bn)
{
#pragma unroll
    for (int r = 0; r < 2; r++) {        // A: 256 rows x 4 segs
        int e = tid + r * 512;
        int row = e >> 2, seg = e & 3;
        CP_ASYNC16(s0 + (uint32_t)row * ROWB + seg * 16,
                   Ah + (size_t)(bm + row) * lda + k0 + seg * 8);
    }
    {
        int row = tid >> 2, seg = tid & 3;   // B: 128 rows x 4 segs
        CP_ASYNC16(s0 + A_BYTES + (uint32_t)row * ROWB + seg * 16,
                   Bh + (size_t)(bn + row) * ldb + k0 + seg * 8);
    }
}

// ACT: 0 none, 1 ELU, 2 GLU (v *= sigmoid(aux)). OUT16: 1 fp16, 0 fp32.
// blockIdx.x < tiles0 -> desc c0, else c1 (z-batched).
template <int ACT, int OUT16>
__global__ __launch_bounds__(512, 1)
void mgemm_k(GDesc c0, GDesc c1, int tiles0)
{
    extern __shared__ char smem[];
    const uint32_t sbase = smem_u32(smem);
    const int tid = threadIdx.x;
    const int bx = blockIdx.x;

    GDesc d;
    int nb, tm, tn;
    if (bx < tiles0) {
        d = c0; nb = 0;
        tm = bx / d.ntN; tn = bx % d.ntN;
    } else {
        d = c1;
        int v = bx - tiles0;
        nb = v / d.tilesPerZ;
        int rem = v % d.tilesPerZ;
        tm = rem / d.ntN; tn = rem % d.ntN;
    }
    const __half* Ah = d.A + (size_t)nb * d.sAn;
    const __half* Bh = d.B + (size_t)nb * d.sBn;
    const float* bias = d.bias + (size_t)nb * d.sBiasN;
    const size_t coff = (size_t)nb * d.sCn;
    const int lda = d.lda, ldb = d.ldb, ldc = d.ldc, K = d.K;
    const int bm = tm * BM, bn = tn * BN;

    const int lane = tid & 31, wid = tid >> 5;
    const int wm = wid & 3, wn = wid >> 2;
    const int lr = lane & 15, lc = lane >> 4;

    float acc[4][4][4];
#pragma unroll
    for (int a = 0; a < 4; a++)
#pragma unroll
        for (int b = 0; b < 4; b++)
#pragma unroll
            for (int c = 0; c < 4; c++) acc[a][b][c] = 0.f;

    const int nk = K / BK;
#pragma unroll
    for (int j = 0; j < 4; j++) {
        if (j < nk)
            load_chunk(sbase + j * STAGEB, tid, j * BK, Ah, lda, bm, Bh, ldb, bn);
        CP_COMMIT();
    }

    int stR = 0, stW = 4;
    for (int i = 0; i < nk; i++) {
        CP_WAIT3();
        __syncthreads();
        const uint32_t sb = sbase + (uint32_t)stR * STAGEB;

#pragma unroll
        for (int ks = 0; ks < 2; ks++) {
            const uint32_t koff = (uint32_t)(ks * 16 + lc * 8) * 2;
            uint32_t ah[4][4];
#pragma unroll
            for (int mt = 0; mt < 4; mt++) {
                uint32_t ra = sb + (uint32_t)(wm * 64 + mt * 16 + lr) * ROWB + koff;
                LDSM4(ah[mt], ra);
            }
#pragma unroll
            for (int nt = 0; nt < 2; nt++) {
                uint32_t rb = sb + A_BYTES +
                              (uint32_t)(wn * 32 + nt * 16 + lr) * ROWB + koff;
                uint32_t bh[4];
                LDSM4(bh, rb);
#pragma unroll
                for (int mt = 0; mt < 4; mt++) {
                    mma16816(acc[mt][nt * 2 + 0], ah[mt], bh[0], bh[2]);
                    mma16816(acc[mt][nt * 2 + 1], ah[mt], bh[1], bh[3]);
                }
            }
        }

        int j = i + 4;
        if (j < nk)
            load_chunk(sbase + (uint32_t)stW * STAGEB, tid, j * BK,
                       Ah, lda, bm, Bh, ldb, bn);
        CP_COMMIT();
        stR = (stR + 1 == NSTAGE) ? 0 : stR + 1;
        stW = (stW + 1 == NSTAGE) ? 0 : stW + 1;
    }

    // Epilogue
    const int rbase = bm + wm * 64 + (lane >> 2);
    const int cbase = bn + wn * 32 + (lane & 3) * 2;
#pragma unroll
    for (int mt = 0; mt < 4; mt++) {
#pragma unroll
        for (int t8 = 0; t8 < 4; t8++) {
            const int r = rbase + mt * 16;
            const int c = cbase + t8 * 8;
            const float b0 = bias[c], b1 = bias[c + 1];
            float v00 = acc[mt][t8][0] + b0, v01 = acc[mt][t8][1] + b1;
            float v10 = acc[mt][t8][2] + b0, v11 = acc[mt][t8][3] + b1;
            if (ACT == 1) {
                v00 = v00 > 0.f ? v00 : expm1f(v00);
                v01 = v01 > 0.f ? v01 : expm1f(v01);
                v10 = v10 > 0.f ? v10 : expm1f(v10);
                v11 = v11 > 0.f ? v11 : expm1f(v11);
            }
            if (ACT == 2) {
                float2 a0 = *(const float2*)(d.Aux + coff + (size_t)r * ldc + c);
                float2 a1 = *(const float2*)(d.Aux + coff + (size_t)(r + 8) * ldc + c);
                v00 *= 1.f / (1.f + expf(-a0.x));
                v01 *= 1.f / (1.f + expf(-a0.y));
                v10 *= 1.f / (1.f + expf(-a1.x));
                v11 *= 1.f / (1.f + expf(-a1.y));
            }
            if (OUT16) {
                __half2 H0 = __floats2half2_rn(v00, v01);
                __half2 H1 = __floats2half2_rn(v10, v11);
                *(uint32_t*)(d.Ch + coff + (size_t)r * ldc + c) =
                    *reinterpret_cast<uint32_t*>(&H0);
                *(uint32_t*)(d.Ch + coff + (size_t)(r + 8) * ldc + c) =
                    *reinterpret_cast<uint32_t*>(&H1);
            } else {
                *(float2*)(d.Cf + coff + (size_t)r * ldc + c) = make_float2(v00, v01);
                *(float2*)(d.Cf + coff + (size_t)(r + 8) * ldc + c) = make_float2(v10, v11);
            }
        }
    }
}

// ---------------- convert fp32 -> fp16 -------------------------------------
__global__ __launch_bounds__(256)
void cvt16_k(const float* __restrict__ src, __half* __restrict__ dst, size_t n)
{
    size_t i = ((size_t)blockIdx.x * blockDim.x + threadIdx.x) * 4;
    if (i >= n) return;
    float4 v = *(const float4*)(src + i);
    __half2 h0 = __floats2half2_rn(v.x, v.y);
    __half2 h1 = __floats2half2_rn(v.z, v.w);
    uint2 o = { *reinterpret_cast<uint32_t*>(&h0), *reinterpret_cast<uint32_t*>(&h1) };
    *(uint2*)((unsigned short*)dst + i) = o;
}

// ---------------- transpose + convert, 4 weights per launch ----------------
// tile: 64(k) x 32(n); half2 stores. z -> (weight, var-batch).
__global__ __launch_bounds__(256)
void tcvt4_k(const float* __restrict__ s0, const float* __restrict__ s1,
             const float* __restrict__ s2, const float* __restrict__ s3,
             __half* __restrict__ d0, __half* __restrict__ d1,
             __half* __restrict__ d2, __half* __restrict__ d3,
             int K, int Ncol, int zPerW)
{
    __shared__ float t[64][33];
    int w = blockIdx.z / zPerW;
    int z = blockIdx.z % zPerW;
    const float* src = (w == 0 ? s0 : w == 1 ? s1 : w == 2 ? s2 : s3)
                       + (size_t)z * K * Ncol;
    __half* dst = (w == 0 ? d0 : w == 1 ? d1 : w == 2 ? d2 : d3)
                  + (size_t)z * K * Ncol;
    int k0 = blockIdx.y * 64, n0 = blockIdx.x * 32;
#pragma unroll
    for (int r = 0; r < 8; r++)
        t[threadIdx.y + 8 * r][threadIdx.x] =
            src[(size_t)(k0 + threadIdx.y + 8 * r) * Ncol + n0 + threadIdx.x];
    __syncthreads();
#pragma unroll
    for (int r = 0; r < 4; r++) {
        int n = threadIdx.y + 8 * r;
        int kk = threadIdx.x;
        __half2 h = __floats2half2_rn(t[2 * kk][n], t[2 * kk + 1][n]);
        *(__half2*)(dst + (size_t)(n0 + n) * K + k0 + 2 * kk) = h;
    }
}

// ---------------- LN(4096) + softmax over variable axis --------------------
__global__ __launch_bounds__(256)
void ln_softmax_k(const float* __restrict__ x, const float* __restrict__ g,
                  const float* __restrict__ gamma, const float* __restrict__ beta,
                  float* __restrict__ w)
{
    __shared__ float s[FEAT];
    __shared__ float red[8];
    const int b = blockIdx.x, t = threadIdx.x;
    const int lane = t & 31, wid = t >> 5;
    const float* xb = x + (size_t)b * FEAT;
    const float* gb = g + (size_t)b * FEAT;

    float lsum = 0.f;
    for (int i = t; i < FEAT; i += 256) {
        float v = xb[i] + gb[i];
        s[i] = v; lsum += v;
    }
#pragma unroll
    for (int o = 16; o; o >>= 1) lsum += __shfl_xor_sync(0xffffffff, lsum, o);
    if (lane == 0) red[wid] = lsum;
    __syncthreads();
    float tot = 0.f;
#pragma unroll
    for (int i = 0; i < 8; i++) tot += red[i];
    float mean = tot * (1.f / FEAT);
    __syncthreads();

    float lvar = 0.f;
    for (int i = t; i < FEAT; i += 256) { float d = s[i] - mean; lvar += d * d; }
#pragma unroll
    for (int o = 16; o; o >>= 1) lvar += __shfl_xor_sync(0xffffffff, lvar, o);
    if (lane == 0) red[wid] = lvar;
    __syncthreads();
    float vtot = 0.f;
#pragma unroll
    for (int i = 0; i < 8; i++) vtot += red[i];
    float rstd = rsqrtf(vtot * (1.f / FEAT) + 1e-5f);

    for (int i = t; i < FEAT; i += 256)
        s[i] = (s[i] - mean) * rstd * gamma[i] + beta[i];
    __syncthreads();

    float c[NVAR];
    float m = -1e30f;
#pragma unroll
    for (int n = 0; n < NVAR; n++) { c[n] = s[n * DDIM + t]; m = fmaxf(m, c[n]); }
    float sum = 0.f;
#pragma unroll
    for (int n = 0; n < NVAR; n++) { c[n] = expf(c[n] - m); sum += c[n]; }
    float inv = 1.f / sum;
    float* wb = w + (size_t)b * FEAT;
#pragma unroll
    for (int n = 0; n < NVAR; n++) wb[n * DDIM + t] = c[n] * inv;
}

// ---------------- per-(b,n) LN(256) + weighted combine (warp per n) --------
__global__ __launch_bounds__(256)
void combine_k(const float* __restrict__ x, const float* __restrict__ gv,
               const float* __restrict__ w, const float* __restrict__ vlng,
               const float* __restrict__ vlnb, float* __restrict__ out)
{
    __shared__ float part[8][256];
    const int b = blockIdx.x, t = threadIdx.x;
    const int lane = t & 31, wrp = t >> 5;

    float accl[8];
#pragma unroll
    for (int j = 0; j < 8; j++) accl[j] = 0.f;

#pragma unroll
    for (int nn = 0; nn < 2; nn++) {
        const int n = wrp * 2 + nn;
        const size_t base = (size_t)b * FEAT + n * DDIM;
        float v[8];
        float sum = 0.f;
#pragma unroll
        for (int j = 0; j < 8; j++) {
            v[j] = x[base + lane + 32 * j] + gv[base + lane + 32 * j];
            sum += v[j];
        }
#pragma unroll
        for (int o = 16; o; o >>= 1) sum += __shfl_xor_sync(0xffffffff, sum, o);
        const float mean = sum * (1.f / DDIM);
        float var = 0.f;
#pragma unroll
        for (int j = 0; j < 8; j++) { float dl = v[j] - mean; var += dl * dl; }
#pragma unroll
        for (int o = 16; o; o >>= 1) var += __shfl_xor_sync(0xffffffff, var, o);
        const float rstd = rsqrtf(var * (1.f / DDIM) + 1e-5f);
#pragma unroll
        for (int j = 0; j < 8; j++) {
            const int dcol = lane + 32 * j;
            float yv = (v[j] - mean) * rstd * vlng[n * DDIM + dcol]
                       + vlnb[n * DDIM + dcol];
            accl[j] += w[base + dcol] * yv;
        }
    }
#pragma unroll
    for (int j = 0; j < 8; j++) part[wrp][lane + 32 * j] = accl[j];
    __syncthreads();
    float s = 0.f;
#pragma unroll
    for (int k = 0; k < 8; k++) s += part[k][t];
    out[(size_t)b * DDIM + t] = s;
}

// ---------------- launch ----------------------------------------------------
extern "C" void kernel_launch(void* const* d_in, const int* in_sizes, int n_in,
                              void* d_out, int out_size)
{
    const float* x    = (const float*)d_in[0];
    const float* vW2  = (const float*)d_in[1];
    const float* vb2  = (const float*)d_in[2];
    const float* vW1  = (const float*)d_in[3];
    const float* vb1  = (const float*)d_in[4];
    const float* vW4  = (const float*)d_in[5];
    const float* vb4  = (const float*)d_in[6];
    const float* vW5  = (const float*)d_in[7];
    const float* vb5  = (const float*)d_in[8];
    const float* vlng = (const float*)d_in[9];
    const float* vlnb = (const float*)d_in[10];
    const float* cW2  = (const float*)d_in[11];
    const float* cb2  = (const float*)d_in[12];
    const float* cW1  = (const float*)d_in[13];
    const float* cb1  = (const float*)d_in[14];
    const float* cW4  = (const float*)d_in[15];
    const float* cb4  = (const float*)d_in[16];
    const float* cW5  = (const float*)d_in[17];
    const float* cb5  = (const float*)d_in[18];
    const float* clng = (const float*)d_in[19];
    const float* clnb = (const float*)d_in[20];
    float* out = (float*)d_out;

    float *buf0, *buf1, *buf2;
    cudaGetSymbolAddress((void**)&buf0, g_buf0);
    cudaGetSymbolAddress((void**)&buf1, g_buf1);
    cudaGetSymbolAddress((void**)&buf2, g_buf2);
    __half *xh, *hh, *eh, *hv, *ev;
    cudaGetSymbolAddress((void**)&xh, g_xh);
    cudaGetSymbolAddress((void**)&hh, g_hh);
    cudaGetSymbolAddress((void**)&eh, g_eh);
    cudaGetSymbolAddress((void**)&hv, g_hv);
    cudaGetSymbolAddress((void**)&ev, g_ev);
    __half *cW2h, *cW1h, *cW4h, *cW5h;
    cudaGetSymbolAddress((void**)&cW2h, g_cW2h);
    cudaGetSymbolAddress((void**)&cW1h, g_cW1h);
    cudaGetSymbolAddress((void**)&cW4h, g_cW4h);
    cudaGetSymbolAddress((void**)&cW5h, g_cW5h);
    __half *vW2h, *vW1h, *vW4h, *vW5h;
    cudaGetSymbolAddress((void**)&vW2h, g_vW2h);
    cudaGetSymbolAddress((void**)&vW1h, g_vW1h);
    cudaGetSymbolAddress((void**)&vW4h, g_vW4h);
    cudaGetSymbolAddress((void**)&vW5h, g_vW5h);

    cudaFuncSetAttribute(mgemm_k<1, 1>, cudaFuncAttributeMaxDynamicSharedMemorySize, GEMM_SMEM);
    cudaFuncSetAttribute(mgemm_k<0, 1>, cudaFuncAttributeMaxDynamicSharedMemorySize, GEMM_SMEM);
    cudaFuncSetAttribute(mgemm_k<0, 0>, cudaFuncAttributeMaxDynamicSharedMemorySize, GEMM_SMEM);
    cudaFuncSetAttribute(mgemm_k<2, 0>, cudaFuncAttributeMaxDynamicSharedMemorySize, GEMM_SMEM);

    const size_t NE = NELEM;

    // ---- conversions ----
    cvt16_k<<<(unsigned)(NE / 1024), 256>>>(x, xh, NE);
    {
        dim3 b(32, 8);
        dim3 gc(FEAT / 32, FEAT / 64, 4);
        tcvt4_k<<<gc, b>>>(cW2, cW1, cW4, cW5, cW2h, cW1h, cW4h, cW5h,
                           FEAT, FEAT, 1);
        dim3 gv(DDIM / 32, DDIM / 64, 4 * NVAR);
        tcvt4_k<<<gv, b>>>(vW2, vW1, vW4, vW5, vW2h, vW1h, vW4h, vW5h,
                           DDIM, DDIM, NVAR);
    }

    // ---- descriptor templates ----
    const int ccTiles = (FEAT / BN) * (BATCH / BM);   // 32*16 = 512
    const int vTilesZ = (DDIM / BN) * (BATCH / BM);   // 2*16  = 32
    const int vTiles  = vTilesZ * NVAR;               // 512
    const unsigned totalTiles = ccTiles + vTiles;     // 1024

    auto mkC = [&](const __half* A, const __half* B, const float* bias,
                   const float* aux, float* cf, __half* ch) {
        GDesc d;
        d.A = A; d.B = B; d.bias = bias; d.Aux = aux; d.Cf = cf; d.Ch = ch;
        d.K = FEAT; d.lda = FEAT; d.ldb = FEAT; d.ldc = FEAT;
        d.sAn = 0; d.sBn = 0; d.sBiasN = 0; d.sCn = 0;
        d.ntN = FEAT / BN; d.tilesPerZ = ccTiles;
        return d;
    };
    auto mkV = [&](const __half* A, const __half* B, const float* bias,
                   const float* aux, float* cf, __half* ch) {
        GDesc d;
        d.A = A; d.B = B; d.bias = bias; d.Aux = aux; d.Cf = cf; d.Ch = ch;
        d.K = DDIM; d.lda = FEAT; d.ldb = DDIM; d.ldc = FEAT;
        d.sAn = DDIM; d.sBn = (long)DDIM * DDIM; d.sBiasN = DDIM; d.sCn = DDIM;
        d.ntN = DDIM / BN; d.tilesPerZ = vTilesZ;
        return d;
    };

    // ---- merged GEMM launches ----
    // L1: h = elu(x@W2+b2), concat + var
    mgemm_k<1, 1><<<totalTiles, 512, GEMM_SMEM>>>(
        mkC(xh, cW2h, cb2, nullptr, nullptr, hh),
        mkV(xh, vW2h, vb2, nullptr, nullptr, hv), ccTiles);
    // L2: e1 = h@W1+b1
    mgemm_k<0, 1><<<totalTiles, 512, GEMM_SMEM>>>(
        mkC(hh, cW1h, cb1, nullptr, nullptr, eh),
        mkV(hv, vW1h, vb1, nullptr, nullptr, ev), ccTiles);
    // L3: t4 = e1@W4+b4 (fp32)
    mgemm_k<0, 0><<<totalTiles, 512, GEMM_SMEM>>>(
        mkC(eh, cW4h, cb4, nullptr, buf0, nullptr),
        mkV(ev, vW4h, vb4, nullptr, buf2, nullptr), ccTiles);
    // L4: g = sigmoid(t4) * (e1@W5+b5)  (GLU fused)
    mgemm_k<2, 0><<<totalTiles, 512, GEMM_SMEM>>>(
        mkC(eh, cW5h, cb5, buf0, buf0, nullptr),
        mkV(ev, vW5h, vb5, buf2, buf2, nullptr), ccTiles);

    // ---- softmax weights + combine ----
    ln_softmax_k<<<BATCH, 256>>>(x, buf0, clng, clnb, buf1);
    combine_k<<<BATCH, 256>>>(x, buf2, buf1, vlng, vlnb, out);
}

// round 9
// speedup vs baseline: 6.4138x; 1.0898x over previous
#include <cuda_runtime.h>
#include <cuda_fp16.h>
#include <math.h>
#include <stdint.h>

#define BATCH 4096
#define NVAR  16
#define DDIM  256
#define FEAT  4096
#define NELEM ((size_t)BATCH * FEAT)     // 16,777,216
#define VWN   ((size_t)NVAR * DDIM * DDIM)

// ---------------- scratch (device globals; allocation forbidden) -----------
__device__ __align__(256) float g_buf0[NELEM];   // concat GLU result
__device__ __align__(256) float g_buf1[NELEM];   // softmax weights
__device__ __align__(256) float g_buf2[NELEM];   // var GLU result
// fp16 activations
__device__ __align__(256) __half g_xh[NELEM];
__device__ __align__(256) __half g_hh[NELEM];    // concat h
__device__ __align__(256) __half g_eh[NELEM];    // concat e1
__device__ __align__(256) __half g_hv[NELEM];    // var h
__device__ __align__(256) __half g_ev[NELEM];    // var e1
// transposed fp16 weights
__device__ __align__(256) __half g_cW2h[NELEM];
__device__ __align__(256) __half g_cW1h[NELEM];
__device__ __align__(256) __half g_cW4h[NELEM];
__device__ __align__(256) __half g_cW5h[NELEM];
__device__ __align__(256) __half g_vW2h[VWN];
__device__ __align__(256) __half g_vW1h[VWN];
__device__ __align__(256) __half g_vW4h[VWN];
__device__ __align__(256) __half g_vW5h[VWN];

// ---------------- helpers ---------------------------------------------------
__device__ __forceinline__ uint32_t smem_u32(const void* p) {
    uint32_t a;
    asm("{ .reg .u64 t; cvta.to.shared.u64 t, %1; cvt.u32.u64 %0, t; }"
        : "=r"(a) : "l"(p));
    return a;
}

#define CP_ASYNC16(dst, src) \
    asm volatile("cp.async.cg.shared.global [%0], [%1], 16;" :: "r"(dst), "l"(src))
#define CP_COMMIT() asm volatile("cp.async.commit_group;" ::: "memory")
#define CP_WAIT3()  asm volatile("cp.async.wait_group 3;" ::: "memory")

#define LDSM4(r, a) \
    asm volatile("ldmatrix.sync.aligned.m8n8.x4.shared.b16 {%0,%1,%2,%3}, [%4];" \
                 : "=r"((r)[0]), "=r"((r)[1]), "=r"((r)[2]), "=r"((r)[3]) : "r"(a))

__device__ __forceinline__ void mma16816(float* d, const uint32_t* a,
                                         uint32_t b0, uint32_t b1) {
    asm volatile(
        "mma.sync.aligned.m16n8k16.row.col.f32.f16.f16.f32 "
        "{%0,%1,%2,%3}, {%4,%5,%6,%7}, {%8,%9}, {%0,%1,%2,%3};"
        : "+f"(d[0]), "+f"(d[1]), "+f"(d[2]), "+f"(d[3])
        : "r"(a[0]), "r"(a[1]), "r"(a[2]), "r"(a[3]), "r"(b0), "r"(b1));
}

// ---------------- merged GEMM (mma.sync fp16) ------------------------------
// BM=128, BN=128, BK=32, 256 threads (8 warps: 2m x 4n), warp tile 64x32.
// 2 CTAs per SM (occupancy doubled vs R8) — smem 100 KB/CTA.
#define BM 128
#define BN 128
#define BK 32
#define ROWB 80
#define A_BYTES (128 * ROWB)             // 10240
#define B_BYTES (128 * ROWB)             // 10240
#define STAGEB (A_BYTES + B_BYTES)       // 20480
#define NSTAGE 5
#define GEMM_SMEM (NSTAGE * STAGEB)      // 102400

struct GDesc {
    const __half* A;
    const __half* B;
    const float*  bias;
    const float*  Aux;
    float*        Cf;
    __half*       Ch;
    int  K, lda, ldb, ldc;
    long sAn, sBn, sBiasN, sCn;
    int  ntN, tilesPerZ;
};

__device__ __forceinline__ void load_chunk(
    uint32_t s0, int tid, int k0,
    const __half* __restrict__ Ah, int lda, int bm,
    const __half* __restrict__ Bh, int ldb, int bn)
{
#pragma unroll
    for (int r = 0; r < 2; r++) {        // A: 128 rows x 4 segs
        int e = tid + r * 256;
        int row = e >> 2, seg = e & 3;
        CP_ASYNC16(s0 + (uint32_t)row * ROWB + seg * 16,
                   Ah + (size_t)(bm + row) * lda + k0 + seg * 8);
    }
#pragma unroll
    for (int r = 0; r < 2; r++) {        // B: 128 rows x 4 segs
        int e = tid + r * 256;
        int row = e >> 2, seg = e & 3;
        CP_ASYNC16(s0 + A_BYTES + (uint32_t)row * ROWB + seg * 16,
                   Bh + (size_t)(bn + row) * ldb + k0 + seg * 8);
    }
}

// ACT: 0 none, 1 ELU, 2 GLU (v *= sigmoid(aux)). OUT16: 1 fp16, 0 fp32.
template <int ACT, int OUT16>
__global__ __launch_bounds__(256, 2)
void mgemm_k(GDesc c0, GDesc c1, int tiles0)
{
    extern __shared__ char smem[];
    const uint32_t sbase = smem_u32(smem);
    const int tid = threadIdx.x;
    const int bx = blockIdx.x;

    GDesc d;
    int nb, tm, tn;
    if (bx < tiles0) {
        d = c0; nb = 0;
        tm = bx / d.ntN; tn = bx % d.ntN;
    } else {
        d = c1;
        int v = bx - tiles0;
        nb = v / d.tilesPerZ;
        int rem = v % d.tilesPerZ;
        tm = rem / d.ntN; tn = rem % d.ntN;
    }
    const __half* Ah = d.A + (size_t)nb * d.sAn;
    const __half* Bh = d.B + (size_t)nb * d.sBn;
    const float* bias = d.bias + (size_t)nb * d.sBiasN;
    const size_t coff = (size_t)nb * d.sCn;
    const int lda = d.lda, ldb = d.ldb, ldc = d.ldc, K = d.K;
    const int bm = tm * BM, bn = tn * BN;

    const int lane = tid & 31, wid = tid >> 5;
    const int wm = wid & 1, wn = wid >> 1;       // 2(m) x 4(n)
    const int lr = lane & 15, lc = lane >> 4;

    float acc[4][4][4];
#pragma unroll
    for (int a = 0; a < 4; a++)
#pragma unroll
        for (int b = 0; b < 4; b++)
#pragma unroll
            for (int c = 0; c < 4; c++) acc[a][b][c] = 0.f;

    const int nk = K / BK;
#pragma unroll
    for (int j = 0; j < 4; j++) {
        if (j < nk)
            load_chunk(sbase + j * STAGEB, tid, j * BK, Ah, lda, bm, Bh, ldb, bn);
        CP_COMMIT();
    }

    int stR = 0, stW = 4;
    for (int i = 0; i < nk; i++) {
        CP_WAIT3();
        __syncthreads();
        const uint32_t sb = sbase + (uint32_t)stR * STAGEB;
        const uint32_t raBase = sb + (uint32_t)(wm * 64 + lr) * ROWB;
        const uint32_t rbBase = sb + A_BYTES + (uint32_t)(wn * 32 + lr) * ROWB;

#pragma unroll
        for (int ks = 0; ks < 2; ks++) {
            const uint32_t koff = (uint32_t)(ks * 16 + lc * 8) * 2;
            uint32_t ah[4][4];
#pragma unroll
            for (int mt = 0; mt < 4; mt++)
                LDSM4(ah[mt], raBase + (uint32_t)(mt * 16) * ROWB + koff);
#pragma unroll
            for (int nt = 0; nt < 2; nt++) {
                uint32_t bh[4];
                LDSM4(bh, rbBase + (uint32_t)(nt * 16) * ROWB + koff);
#pragma unroll
                for (int mt = 0; mt < 4; mt++) {
                    mma16816(acc[mt][nt * 2 + 0], ah[mt], bh[0], bh[2]);
                    mma16816(acc[mt][nt * 2 + 1], ah[mt], bh[1], bh[3]);
                }
            }
        }

        int j = i + 4;
        if (j < nk)
            load_chunk(sbase + (uint32_t)stW * STAGEB, tid, j * BK,
                       Ah, lda, bm, Bh, ldb, bn);
        CP_COMMIT();
        stR = (stR + 1 == NSTAGE) ? 0 : stR + 1;
        stW = (stW + 1 == NSTAGE) ? 0 : stW + 1;
    }

    // Epilogue: warp tile 64x32.
    const int rbase = bm + wm * 64 + (lane >> 2);
    const int cbase = bn + wn * 32 + (lane & 3) * 2;
#pragma unroll
    for (int mt = 0; mt < 4; mt++) {
#pragma unroll
        for (int t8 = 0; t8 < 4; t8++) {
            const int r = rbase + mt * 16;
            const int c = cbase + t8 * 8;
            const float b0 = bias[c], b1 = bias[c + 1];
            float v00 = acc[mt][t8][0] + b0, v01 = acc[mt][t8][1] + b1;
            float v10 = acc[mt][t8][2] + b0, v11 = acc[mt][t8][3] + b1;
            if (ACT == 1) {
                v00 = v00 > 0.f ? v00 : expm1f(v00);
                v01 = v01 > 0.f ? v01 : expm1f(v01);
                v10 = v10 > 0.f ? v10 : expm1f(v10);
                v11 = v11 > 0.f ? v11 : expm1f(v11);
            }
            if (ACT == 2) {
                float2 a0 = *(const float2*)(d.Aux + coff + (size_t)r * ldc + c);
                float2 a1 = *(const float2*)(d.Aux + coff + (size_t)(r + 8) * ldc + c);
                v00 *= 1.f / (1.f + expf(-a0.x));
                v01 *= 1.f / (1.f + expf(-a0.y));
                v10 *= 1.f / (1.f + expf(-a1.x));
                v11 *= 1.f / (1.f + expf(-a1.y));
            }
            if (OUT16) {
                __half2 H0 = __floats2half2_rn(v00, v01);
                __half2 H1 = __floats2half2_rn(v10, v11);
                *(uint32_t*)(d.Ch + coff + (size_t)r * ldc + c) =
                    *reinterpret_cast<uint32_t*>(&H0);
                *(uint32_t*)(d.Ch + coff + (size_t)(r + 8) * ldc + c) =
                    *reinterpret_cast<uint32_t*>(&H1);
            } else {
                *(float2*)(d.Cf + coff + (size_t)r * ldc + c) = make_float2(v00, v01);
                *(float2*)(d.Cf + coff + (size_t)(r + 8) * ldc + c) = make_float2(v10, v11);
            }
        }
    }
}

// ---------------- convert fp32 -> fp16 -------------------------------------
__global__ __launch_bounds__(256)
void cvt16_k(const float* __restrict__ src, __half* __restrict__ dst, size_t n)
{
    size_t i = ((size_t)blockIdx.x * blockDim.x + threadIdx.x) * 4;
    if (i >= n) return;
    float4 v = *(const float4*)(src + i);
    __half2 h0 = __floats2half2_rn(v.x, v.y);
    __half2 h1 = __floats2half2_rn(v.z, v.w);
    uint2 o = { *reinterpret_cast<uint32_t*>(&h0), *reinterpret_cast<uint32_t*>(&h1) };
    *(uint2*)((unsigned short*)dst + i) = o;
}

// ---------------- transpose + convert, 4 weights per launch ----------------
__global__ __launch_bounds__(256)
void tcvt4_k(const float* __restrict__ s0, const float* __restrict__ s1,
             const float* __restrict__ s2, const float* __restrict__ s3,
             __half* __restrict__ d0, __half* __restrict__ d1,
             __half* __restrict__ d2, __half* __restrict__ d3,
             int K, int Ncol, int zPerW)
{
    __shared__ float t[64][33];
    int w = blockIdx.z / zPerW;
    int z = blockIdx.z % zPerW;
    const float* src = (w == 0 ? s0 : w == 1 ? s1 : w == 2 ? s2 : s3)
                       + (size_t)z * K * Ncol;
    __half* dst = (w == 0 ? d0 : w == 1 ? d1 : w == 2 ? d2 : d3)
                  + (size_t)z * K * Ncol;
    int k0 = blockIdx.y * 64, n0 = blockIdx.x * 32;
#pragma unroll
    for (int r = 0; r < 8; r++)
        t[threadIdx.y + 8 * r][threadIdx.x] =
            src[(size_t)(k0 + threadIdx.y + 8 * r) * Ncol + n0 + threadIdx.x];
    __syncthreads();
#pragma unroll
    for (int r = 0; r < 4; r++) {
        int n = threadIdx.y + 8 * r;
        int kk = threadIdx.x;
        __half2 h = __floats2half2_rn(t[2 * kk][n], t[2 * kk + 1][n]);
        *(__half2*)(dst + (size_t)(n0 + n) * K + k0 + 2 * kk) = h;
    }
}

// ---------------- LN(4096) + softmax over variable axis --------------------
__global__ __launch_bounds__(256)
void ln_softmax_k(const float* __restrict__ x, const float* __restrict__ g,
                  const float* __restrict__ gamma, const float* __restrict__ beta,
                  float* __restrict__ w)
{
    __shared__ float s[FEAT];
    __shared__ float red[8];
    const int b = blockIdx.x, t = threadIdx.x;
    const int lane = t & 31, wid = t >> 5;
    const float* xb = x + (size_t)b * FEAT;
    const float* gb = g + (size_t)b * FEAT;

    float lsum = 0.f;
    for (int i = t; i < FEAT; i += 256) {
        float v = xb[i] + gb[i];
        s[i] = v; lsum += v;
    }
#pragma unroll
    for (int o = 16; o; o >>= 1) lsum += __shfl_xor_sync(0xffffffff, lsum, o);
    if (lane == 0) red[wid] = lsum;
    __syncthreads();
    float tot = 0.f;
#pragma unroll
    for (int i = 0; i < 8; i++) tot += red[i];
    float mean = tot * (1.f / FEAT);
    __syncthreads();

    float lvar = 0.f;
    for (int i = t; i < FEAT; i += 256) { float d = s[i] - mean; lvar += d * d; }
#pragma unroll
    for (int o = 16; o; o >>= 1) lvar += __shfl_xor_sync(0xffffffff, lvar, o);
    if (lane == 0) red[wid] = lvar;
    __syncthreads();
    float vtot = 0.f;
#pragma unroll
    for (int i = 0; i < 8; i++) vtot += red[i];
    float rstd = rsqrtf(vtot * (1.f / FEAT) + 1e-5f);

    for (int i = t; i < FEAT; i += 256)
        s[i] = (s[i] - mean) * rstd * gamma[i] + beta[i];
    __syncthreads();

    float c[NVAR];
    float m = -1e30f;
#pragma unroll
    for (int n = 0; n < NVAR; n++) { c[n] = s[n * DDIM + t]; m = fmaxf(m, c[n]); }
    float sum = 0.f;
#pragma unroll
    for (int n = 0; n < NVAR; n++) { c[n] = expf(c[n] - m); sum += c[n]; }
    float inv = 1.f / sum;
    float* wb = w + (size_t)b * FEAT;
#pragma unroll
    for (int n = 0; n < NVAR; n++) wb[n * DDIM + t] = c[n] * inv;
}

// ---------------- per-(b,n) LN(256) + weighted combine (warp per n) --------
__global__ __launch_bounds__(256)
void combine_k(const float* __restrict__ x, const float* __restrict__ gv,
               const float* __restrict__ w, const float* __restrict__ vlng,
               const float* __restrict__ vlnb, float* __restrict__ out)
{
    __shared__ float part[8][256];
    const int b = blockIdx.x, t = threadIdx.x;
    const int lane = t & 31, wrp = t >> 5;

    float accl[8];
#pragma unroll
    for (int j = 0; j < 8; j++) accl[j] = 0.f;

#pragma unroll
    for (int nn = 0; nn < 2; nn++) {
        const int n = wrp * 2 + nn;
        const size_t base = (size_t)b * FEAT + n * DDIM;
        float v[8];
        float sum = 0.f;
#pragma unroll
        for (int j = 0; j < 8; j++) {
            v[j] = x[base + lane + 32 * j] + gv[base + lane + 32 * j];
            sum += v[j];
        }
#pragma unroll
        for (int o = 16; o; o >>= 1) sum += __shfl_xor_sync(0xffffffff, sum, o);
        const float mean = sum * (1.f / DDIM);
        float var = 0.f;
#pragma unroll
        for (int j = 0; j < 8; j++) { float dl = v[j] - mean; var += dl * dl; }
#pragma unroll
        for (int o = 16; o; o >>= 1) var += __shfl_xor_sync(0xffffffff, var, o);
        const float rstd = rsqrtf(var * (1.f / DDIM) + 1e-5f);
#pragma unroll
        for (int j = 0; j < 8; j++) {
            const int dcol = lane + 32 * j;
            float yv = (v[j] - mean) * rstd * vlng[n * DDIM + dcol]
                       + vlnb[n * DDIM + dcol];
            accl[j] += w[base + dcol] * yv;
        }
    }
#pragma unroll
    for (int j = 0; j < 8; j++) part[wrp][lane + 32 * j] = accl[j];
    __syncthreads();
    float s = 0.f;
#pragma unroll
    for (int k = 0; k < 8; k++) s += part[k][t];
    out[(size_t)b * DDIM + t] = s;
}

// ---------------- launch ----------------------------------------------------
extern "C" void kernel_launch(void* const* d_in, const int* in_sizes, int n_in,
                              void* d_out, int out_size)
{
    const float* x    = (const float*)d_in[0];
    const float* vW2  = (const float*)d_in[1];
    const float* vb2  = (const float*)d_in[2];
    const float* vW1  = (const float*)d_in[3];
    const float* vb1  = (const float*)d_in[4];
    const float* vW4  = (const float*)d_in[5];
    const float* vb4  = (const float*)d_in[6];
    const float* vW5  = (const float*)d_in[7];
    const float* vb5  = (const float*)d_in[8];
    const float* vlng = (const float*)d_in[9];
    const float* vlnb = (const float*)d_in[10];
    const float* cW2  = (const float*)d_in[11];
    const float* cb2  = (const float*)d_in[12];
    const float* cW1  = (const float*)d_in[13];
    const float* cb1  = (const float*)d_in[14];
    const float* cW4  = (const float*)d_in[15];
    const float* cb4  = (const float*)d_in[16];
    const float* cW5  = (const float*)d_in[17];
    const float* cb5  = (const float*)d_in[18];
    const float* clng = (const float*)d_in[19];
    const float* clnb = (const float*)d_in[20];
    float* out = (float*)d_out;

    float *buf0, *buf1, *buf2;
    cudaGetSymbolAddress((void**)&buf0, g_buf0);
    cudaGetSymbolAddress((void**)&buf1, g_buf1);
    cudaGetSymbolAddress((void**)&buf2, g_buf2);
    __half *xh, *hh, *eh, *hv, *ev;
    cudaGetSymbolAddress((void**)&xh, g_xh);
    cudaGetSymbolAddress((void**)&hh, g_hh);
    cudaGetSymbolAddress((void**)&eh, g_eh);
    cudaGetSymbolAddress((void**)&hv, g_hv);
    cudaGetSymbolAddress((void**)&ev, g_ev);
    __half *cW2h, *cW1h, *cW4h, *cW5h;
    cudaGetSymbolAddress((void**)&cW2h, g_cW2h);
    cudaGetSymbolAddress((void**)&cW1h, g_cW1h);
    cudaGetSymbolAddress((void**)&cW4h, g_cW4h);
    cudaGetSymbolAddress((void**)&cW5h, g_cW5h);
    __half *vW2h, *vW1h, *vW4h, *vW5h;
    cudaGetSymbolAddress((void**)&vW2h, g_vW2h);
    cudaGetSymbolAddress((void**)&vW1h, g_vW1h);
    cudaGetSymbolAddress((void**)&vW4h, g_vW4h);
    cudaGetSymbolAddress((void**)&vW5h, g_vW5h);

    cudaFuncSetAttribute(mgemm_k<1, 1>, cudaFuncAttributeMaxDynamicSharedMemorySize, GEMM_SMEM);
    cudaFuncSetAttribute(mgemm_k<0, 1>, cudaFuncAttributeMaxDynamicSharedMemorySize, GEMM_SMEM);
    cudaFuncSetAttribute(mgemm_k<0, 0>, cudaFuncAttributeMaxDynamicSharedMemorySize, GEMM_SMEM);
    cudaFuncSetAttribute(mgemm_k<2, 0>, cudaFuncAttributeMaxDynamicSharedMemorySize, GEMM_SMEM);

    const size_t NE = NELEM;

    // ---- conversions ----
    cvt16_k<<<(unsigned)(NE / 1024), 256>>>(x, xh, NE);
    {
        dim3 b(32, 8);
        dim3 gc(FEAT / 32, FEAT / 64, 4);
        tcvt4_k<<<gc, b>>>(cW2, cW1, cW4, cW5, cW2h, cW1h, cW4h, cW5h,
                           FEAT, FEAT, 1);
        dim3 gv(DDIM / 32, DDIM / 64, 4 * NVAR);
        tcvt4_k<<<gv, b>>>(vW2, vW1, vW4, vW5, vW2h, vW1h, vW4h, vW5h,
                           DDIM, DDIM, NVAR);
    }

    // ---- descriptor templates ----
    const int ccTiles = (FEAT / BN) * (BATCH / BM);   // 32*32 = 1024
    const int vTilesZ = (DDIM / BN) * (BATCH / BM);   // 2*32  = 64
    const int vTiles  = vTilesZ * NVAR;               // 1024
    const unsigned totalTiles = ccTiles + vTiles;     // 2048

    auto mkC = [&](const __half* A, const __half* B, const float* bias,
                   const float* aux, float* cf, __half* ch) {
        GDesc d;
        d.A = A; d.B = B; d.bias = bias; d.Aux = aux; d.Cf = cf; d.Ch = ch;
        d.K = FEAT; d.lda = FEAT; d.ldb = FEAT; d.ldc = FEAT;
        d.sAn = 0; d.sBn = 0; d.sBiasN = 0; d.sCn = 0;
        d.ntN = FEAT / BN; d.tilesPerZ = ccTiles;
        return d;
    };
    auto mkV = [&](const __half* A, const __half* B, const float* bias,
                   const float* aux, float* cf, __half* ch) {
        GDesc d;
        d.A = A; d.B = B; d.bias = bias; d.Aux = aux; d.Cf = cf; d.Ch = ch;
        d.K = DDIM; d.lda = FEAT; d.ldb = DDIM; d.ldc = FEAT;
        d.sAn = DDIM; d.sBn = (long)DDIM * DDIM; d.sBiasN = DDIM; d.sCn = DDIM;
        d.ntN = DDIM / BN; d.tilesPerZ = vTilesZ;
        return d;
    };

    // ---- merged GEMM launches ----
    mgemm_k<1, 1><<<totalTiles, 256, GEMM_SMEM>>>(
        mkC(xh, cW2h, cb2, nullptr, nullptr, hh),
        mkV(xh, vW2h, vb2, nullptr, nullptr, hv), ccTiles);
    mgemm_k<0, 1><<<totalTiles, 256, GEMM_SMEM>>>(
        mkC(hh, cW1h, cb1, nullptr, nullptr, eh),
        mkV(hv, vW1h, vb1, nullptr, nullptr, ev), ccTiles);
    mgemm_k<0, 0><<<totalTiles, 256, GEMM_SMEM>>>(
        mkC(eh, cW4h, cb4, nullptr, buf0, nullptr),
        mkV(ev, vW4h, vb4, nullptr, buf2, nullptr), ccTiles);
    mgemm_k<2, 0><<<totalTiles, 256, GEMM_SMEM>>>(
        mkC(eh, cW5h, cb5, buf0, buf0, nullptr),
        mkV(ev, vW5h, vb5, buf2, buf2, nullptr), ccTiles);

    // ---- softmax weights + combine ----
    ln_softmax_k<<<BATCH, 256>>>(x, buf0, clng, clnb, buf1);
    combine_k<<<BATCH, 256>>>(x, buf2, buf1, vlng, vlnb, out);
}